// round 8
// baseline (speedup 1.0000x reference)
#include <cuda_runtime.h>
#include <math.h>

#define HD 256
#define WD 256
#define NPIX 65536
#define CD 128
#define FC 1024
#define HS 512
#define WSEG 512
#define CS 32
#define KTOP 2000
#define MAXOUT 500
#define CROP 48
#define CI 64
#define CAND_CAP 4096

#define OFF_SCORES 0
#define OFF_DEC 500
#define OFF_INST 1500
#define OFF_COORD 1153500

// ---------------- scratch (device globals; no allocation allowed) ----------------
__device__ float g_x1[(size_t)NPIX * FC];            // 256 MB
__device__ float g_x2[(size_t)NPIX * FC];            // 256 MB
__device__ float g_logits[NPIX];
__device__ unsigned g_keys[NPIX];
__device__ float2 g_regv[NPIX];
__device__ unsigned g_counts[256];
__device__ unsigned g_prefix;
__device__ unsigned g_maskbits;
__device__ int g_want;
__device__ int g_ncand;
__device__ unsigned long long g_cand[CAND_CAP];
__device__ unsigned g_topidx[KTOP];
__device__ int g_start[MAXOUT * 2];
__device__ float g_h[(size_t)MAXOUT * CROP * CROP * CI];   // 295 MB

// ---------------- init ----------------
__global__ void init_kernel() {
    int t = threadIdx.x;
    if (t < 256) g_counts[t] = 0;
    if (t == 0) { g_prefix = 0; g_maskbits = 0; g_want = KTOP; g_ncand = 0; }
    for (int i = t; i < CAND_CAP; i += blockDim.x) g_cand[i] = 0ull;
}

// ---------------- GEMM: C[M,1024] = relu(A*B + bias) ----------------
// IM2COL=1: A = detection features [256,256,128], virtual A[m,k], k=(dy*3+dx)*128+c
// IM2COL=0: A = dense [65536,1024]
#define BM 128
#define BN 128
#define BK 16
#define LDP 132   // smem leading dim with pad

template <int IM2COL>
__global__ __launch_bounds__(256, 2) void gemm_relu(
    const float* __restrict__ A, const float* __restrict__ B,
    const float* __restrict__ bias, float* __restrict__ C, int ksteps)
{
    __shared__ float As[BK * LDP];
    __shared__ float Bs[BK * LDP];

    int tid = threadIdx.x;
    int tx = tid & 15, ty = tid >> 4;
    int mb = blockIdx.y * BM;
    int nb = blockIdx.x * BN;

    int y0 = 0, x0 = 0;
    if (IM2COL) { y0 = blockIdx.y >> 1; x0 = (blockIdx.y & 1) * 128; }

    float acc[8][8];
#pragma unroll
    for (int i = 0; i < 8; i++)
#pragma unroll
        for (int j = 0; j < 8; j++) acc[i][j] = 0.f;

    for (int kt = 0; kt < ksteps; ++kt) {
        // load A tile (128 pixels x 16 k)
#pragma unroll
        for (int s = 0; s < 2; ++s) {
            int id = tid + s * 256;
            int pix = id >> 2;
            int ch = (id & 3) * 4;
            float4 v;
            if (IM2COL) {
                int off = kt >> 3;
                int c0 = (kt & 7) * 16;
                int dy = off / 3 - 1, dx = off % 3 - 1;
                int yy = y0 + dy;
                int xx = x0 + pix + dx;
                if ((unsigned)yy < 256u && (unsigned)xx < 256u)
                    v = *(const float4*)&A[((size_t)((yy << 8) + xx)) * 128 + c0 + ch];
                else
                    v = make_float4(0.f, 0.f, 0.f, 0.f);
            } else {
                v = *(const float4*)&A[(size_t)(mb + pix) * 1024 + kt * 16 + ch];
            }
            As[(ch + 0) * LDP + pix] = v.x;
            As[(ch + 1) * LDP + pix] = v.y;
            As[(ch + 2) * LDP + pix] = v.z;
            As[(ch + 3) * LDP + pix] = v.w;
        }
        // load B tile (16 k x 128 n) ; global row = kt*16+row works for both convs
#pragma unroll
        for (int s = 0; s < 2; ++s) {
            int id = tid + s * 256;
            int row = id >> 5;
            int n4 = (id & 31) * 4;
            float4 v = *(const float4*)&B[(size_t)(kt * 16 + row) * 1024 + nb + n4];
            *(float4*)&Bs[row * LDP + n4] = v;
        }
        __syncthreads();
#pragma unroll
        for (int kk = 0; kk < BK; ++kk) {
            float4 a0 = *(float4*)&As[kk * LDP + ty * 8];
            float4 a1 = *(float4*)&As[kk * LDP + ty * 8 + 4];
            float4 b0 = *(float4*)&Bs[kk * LDP + tx * 8];
            float4 b1 = *(float4*)&Bs[kk * LDP + tx * 8 + 4];
            float a[8] = {a0.x, a0.y, a0.z, a0.w, a1.x, a1.y, a1.z, a1.w};
            float b[8] = {b0.x, b0.y, b0.z, b0.w, b1.x, b1.y, b1.z, b1.w};
#pragma unroll
            for (int i = 0; i < 8; i++)
#pragma unroll
                for (int j = 0; j < 8; j++) acc[i][j] += a[i] * b[j];
        }
        __syncthreads();
    }
    // epilogue: bias + relu
#pragma unroll
    for (int i = 0; i < 8; i++) {
        size_t row = (size_t)(mb + ty * 8 + i) * 1024 + nb;
#pragma unroll
        for (int j = 0; j < 8; j += 4) {
            int n = tx * 8 + j;
            float4 o;
            o.x = fmaxf(acc[i][j + 0] + bias[nb + n + 0], 0.f);
            o.y = fmaxf(acc[i][j + 1] + bias[nb + n + 1], 0.f);
            o.z = fmaxf(acc[i][j + 2] + bias[nb + n + 2], 0.f);
            o.w = fmaxf(acc[i][j + 3] + bias[nb + n + 3], 0.f);
            *(float4*)&C[row + n] = o;
        }
    }
}

// ---------------- heads: score logit + reg per pixel ----------------
__global__ void heads_kernel(const float* __restrict__ x2,
                             const float* __restrict__ Ws, const float* __restrict__ bs,
                             const float* __restrict__ Wr, const float* __restrict__ br)
{
    int gid = blockIdx.x * blockDim.x + threadIdx.x;
    int m = gid >> 5;
    int lane = threadIdx.x & 31;
    if (m >= NPIX) return;
    const float* xr = x2 + (size_t)m * 1024;
    float s = 0.f, r0 = 0.f, r1 = 0.f;
    for (int c = lane; c < 1024; c += 32) {
        float x = xr[c];
        s += x * Ws[c];
        r0 += x * Wr[2 * c];
        r1 += x * Wr[2 * c + 1];
    }
#pragma unroll
    for (int o = 16; o; o >>= 1) {
        s  += __shfl_down_sync(0xFFFFFFFFu, s, o);
        r0 += __shfl_down_sync(0xFFFFFFFFu, r0, o);
        r1 += __shfl_down_sync(0xFFFFFFFFu, r1, o);
    }
    if (lane == 0) {
        float logit = s + bs[0];
        g_logits[m] = logit;
        unsigned b = __float_as_uint(logit);
        g_keys[m] = (b & 0x80000000u) ? ~b : (b | 0x80000000u);
        g_regv[m] = make_float2(r0 + br[0], r1 + br[1]);
    }
}

// ---------------- radix select (find key of 2000th largest) ----------------
__global__ void rs_hist(int shift) {
    __shared__ unsigned hc[256];
    int t = threadIdx.x;
    hc[t] = 0;
    __syncthreads();
    int m = blockIdx.x * 256 + t;
    unsigned key = g_keys[m];
    if ((key & g_maskbits) == g_prefix)
        atomicAdd(&hc[(key >> shift) & 0xFFu], 1u);
    __syncthreads();
    if (hc[t]) atomicAdd(&g_counts[t], hc[t]);
}

__global__ void rs_scan(int shift) {
    int want = g_want;
    unsigned cum = 0;
    int sel = 0;
    for (int b = 255; b >= 0; b--) {
        unsigned c = g_counts[b];
        if (cum + c >= (unsigned)want) { sel = b; g_want = want - (int)cum; break; }
        cum += c;
    }
    g_prefix |= ((unsigned)sel) << shift;
    g_maskbits |= 0xFFu << shift;
    for (int b = 0; b < 256; b++) g_counts[b] = 0;
}

__global__ void rs_gather() {
    int m = blockIdx.x * 256 + threadIdx.x;
    unsigned key = g_keys[m];
    if (key >= g_prefix) {   // after 4 passes g_prefix == exact threshold key
        int p = atomicAdd(&g_ncand, 1);
        if (p < CAND_CAP)
            g_cand[p] = ((unsigned long long)key << 32) | (unsigned)(~m);
    }
}

// ---------------- bitonic sort (desc by key, asc by index) ----------------
__global__ void sort_kernel() {
    __shared__ unsigned long long s[CAND_CAP];
    int tid = threadIdx.x;
    for (int i = tid; i < CAND_CAP; i += 1024) s[i] = g_cand[i];
    __syncthreads();
    for (int k = 2; k <= CAND_CAP; k <<= 1) {
        for (int j = k >> 1; j > 0; j >>= 1) {
#pragma unroll
            for (int q = 0; q < 4; q++) {
                int t = tid + q * 1024;
                int ixj = t ^ j;
                if (ixj > t) {
                    unsigned long long a = s[t], b = s[ixj];
                    bool seg = (t & k) == 0;          // descending segment
                    if (seg ? (a < b) : (a > b)) { s[t] = b; s[ixj] = a; }
                }
            }
            __syncthreads();
        }
    }
    for (int i = tid; i < KTOP; i += 1024)
        g_topidx[i] = ~((unsigned)(s[i] & 0xFFFFFFFFull));
}

// ---------------- NMS + final top-500 selection ----------------
__global__ void nms_kernel(float* __restrict__ d_out) {
    __shared__ float sy[KTOP], sx[KTOP], slog[KTOP];
    __shared__ unsigned char supp[KTOP];
    __shared__ int sel[MAXOUT];
    __shared__ float selsc[MAXOUT];
    int tid = threadIdx.x;
    for (int i = tid; i < KTOP; i += 1024) {
        unsigned idx = g_topidx[i];
        int y = idx >> 8;
        int x = idx & 255;
        float2 r = g_regv[idx];
        sy[i] = (float)y + 0.5f + r.x;
        sx[i] = (float)x + 0.5f + r.y;
        slog[i] = g_logits[idx];
        supp[i] = 0;
    }
    __syncthreads();
    for (int i = 0; i < KTOP; i++) {
        if (!supp[i]) {
            float by = sy[i], bx = sx[i];
#pragma unroll
            for (int q = 0; q < 2; q++) {
                int j = tid + q * 1024;
                if (j > i && j < KTOP && !supp[j]) {
                    float dy = sy[j] - by;
                    float dx = sx[j] - bx;
                    if (dy * dy + dx * dx < 1.0f) supp[j] = 1;
                }
            }
        }
        __syncthreads();
    }
    if (tid == 0) {
        int c = 0;
        for (int i = 0; i < KTOP && c < MAXOUT; i++)
            if (!supp[i]) { sel[c] = i; selsc[c] = 1.f / (1.f + expf(-slog[i])); c++; }
        for (int i = 0; i < KTOP && c < MAXOUT; i++)
            if (supp[i]) { sel[c] = i; selsc[c] = -1.f; c++; }
    }
    __syncthreads();
    if (tid < MAXOUT) {
        int i = sel[tid];
        d_out[OFF_SCORES + tid] = selsc[tid];
        float dy = sy[i] * 4.f;   // decoded pixel coords (exact: /256 * 1024)
        float dx = sx[i] * 4.f;
        d_out[OFF_DEC + 2 * tid] = dy;
        d_out[OFF_DEC + 2 * tid + 1] = dx;
        float ry = rintf(sy[i] * 2.f - 24.f);   // round-half-even like jnp.round
        float rx = rintf(sx[i] * 2.f - 24.f);
        int syi = (int)fminf(fmaxf(ry, 0.f), (float)(HS - CROP));
        int sxi = (int)fminf(fmaxf(rx, 0.f), (float)(WSEG - CROP));
        g_start[2 * tid] = syi;
        g_start[2 * tid + 1] = sxi;
    }
}

// ---------------- instance conv1: crop -> relu(conv3x3 32->64) ----------------
// grid (500, 3), 256 threads, strip of 16 output rows. smem: input 18x50x32 (pad 33) + full Wi.
#define SMEM_I_FLOATS (18 * 50 * 33 + 288 * 64)
__global__ __launch_bounds__(256) void convi_kernel(
    const float* __restrict__ seg, const float* __restrict__ Wi, const float* __restrict__ bi)
{
    extern __shared__ float sm[];
    float* in_s = sm;                  // [(rr*50+cc)*33 + ci]
    float* ws = sm + 18 * 50 * 33;     // [k*64 + co], k = (dy*3+dx)*32+ci

    int crop = blockIdx.x;
    int strip = blockIdx.y;
    int tid = threadIdx.x;

    int sy = g_start[2 * crop], sx = g_start[2 * crop + 1];

    for (int id = tid; id < 288 * 64; id += 256) ws[id] = Wi[id];

    int r0 = strip * 16 - 1;
    for (int id = tid; id < 18 * 50 * 32; id += 256) {
        int ci = id & 31;
        int rest = id >> 5;
        int cc = rest % 50;
        int rr = rest / 50;
        int rin = r0 + rr;
        int cin = cc - 1;
        float v = 0.f;
        if ((unsigned)rin < 48u && (unsigned)cin < 48u)
            v = seg[((size_t)(sy + rin) * 512 + (sx + cin)) * 32 + ci];
        in_s[(rr * 50 + cc) * 33 + ci] = v;
    }
    __syncthreads();

    int r = tid >> 4;          // 0..15 output row within strip
    int cg = tid & 15;         // column group of 3
    int c0 = cg * 3;
    int r_out = strip * 16 + r;

    for (int cog = 0; cog < 4; cog++) {
        float acc[48];
#pragma unroll
        for (int i = 0; i < 48; i++) acc[i] = 0.f;
#pragma unroll
        for (int dy = 0; dy < 3; dy++) {
#pragma unroll
            for (int dx = 0; dx < 3; dx++) {
                const float* wbase = ws + ((dy * 3 + dx) * 32) * 64 + cog * 16;
                const float* ibase = in_s + ((r + dy) * 50 + (c0 + dx)) * 33;
#pragma unroll 4
                for (int ci = 0; ci < 32; ci++) {
                    float4 w0 = *(const float4*)(wbase + ci * 64);
                    float4 w1 = *(const float4*)(wbase + ci * 64 + 4);
                    float4 w2 = *(const float4*)(wbase + ci * 64 + 8);
                    float4 w3 = *(const float4*)(wbase + ci * 64 + 12);
                    float wv[16] = {w0.x, w0.y, w0.z, w0.w, w1.x, w1.y, w1.z, w1.w,
                                    w2.x, w2.y, w2.z, w2.w, w3.x, w3.y, w3.z, w3.w};
                    float v0 = ibase[ci];
                    float v1 = ibase[33 + ci];
                    float v2 = ibase[66 + ci];
#pragma unroll
                    for (int co = 0; co < 16; co++) {
                        acc[co] += v0 * wv[co];
                        acc[16 + co] += v1 * wv[co];
                        acc[32 + co] += v2 * wv[co];
                    }
                }
            }
        }
#pragma unroll
        for (int col = 0; col < 3; col++) {
            int c = c0 + col;
            float* dst = g_h + (((size_t)crop * 48 + r_out) * 48 + c) * 64 + cog * 16;
#pragma unroll
            for (int j = 0; j < 16; j += 4) {
                float4 o;
                o.x = fmaxf(acc[col * 16 + j + 0] + bi[cog * 16 + j + 0], 0.f);
                o.y = fmaxf(acc[col * 16 + j + 1] + bi[cog * 16 + j + 1], 0.f);
                o.z = fmaxf(acc[col * 16 + j + 2] + bi[cog * 16 + j + 2], 0.f);
                o.w = fmaxf(acc[col * 16 + j + 3] + bi[cog * 16 + j + 3], 0.f);
                *(float4*)(dst + j) = o;
            }
        }
    }
}

// ---------------- instance conv2: sigmoid(conv3x3 64->1) + coords ----------------
// grid (500, 6), 384 threads, strip of 8 output rows.
#define SMEM_O_FLOATS (10 * 48 * 65 + 576)
__global__ __launch_bounds__(384) void convo_kernel(
    const float* __restrict__ Wo, const float* __restrict__ bo, float* __restrict__ d_out)
{
    extern __shared__ float sm[];
    float* h_s = sm;                    // [(rr*48+cc)*65 + ci]
    float* wsm = sm + 10 * 48 * 65;     // [576]

    int crop = blockIdx.x;
    int strip = blockIdx.y;
    int tid = threadIdx.x;

    // FIX (R6 bug): 576 weights, 384 threads -> must stride, else wsm[384..575] is garbage
    for (int i = tid; i < 576; i += 384) wsm[i] = Wo[i];

    int r0 = strip * 8 - 1;
    for (int id = tid; id < 10 * 48 * 64; id += 384) {
        int co = id & 63;
        int rest = id >> 6;
        int cc = rest % 48;
        int rr = rest / 48;
        int rin = r0 + rr;
        float v = 0.f;
        if ((unsigned)rin < 48u)
            v = g_h[(((size_t)crop * 48 + rin) * 48 + cc) * 64 + co];
        h_s[(rr * 48 + cc) * 65 + co] = v;
    }
    __syncthreads();

    int r = tid / 48;
    int c = tid % 48;
    float acc = bo[0];
#pragma unroll
    for (int dy = 0; dy < 3; dy++) {
#pragma unroll
        for (int dx = 0; dx < 3; dx++) {
            int hc = c + dx - 1;
            if ((unsigned)hc < 48u) {
                const float* hb = h_s + ((r + dy) * 48 + hc) * 65;
                const float* wb = wsm + (dy * 3 + dx) * 64;
#pragma unroll 8
                for (int ci = 0; ci < 64; ci++) acc += hb[ci] * wb[ci];
            }
        }
    }
    float o = 1.f / (1.f + expf(-acc));
    int r_out = strip * 8 + r;
    size_t oi = ((size_t)crop * 48 + r_out) * 48 + c;
    d_out[OFF_INST + oi] = o;
    int syi = g_start[2 * crop], sxi = g_start[2 * crop + 1];
    d_out[OFF_COORD + oi * 2] = (float)(syi + r_out);
    d_out[OFF_COORD + oi * 2 + 1] = (float)(sxi + c);
}

// ---------------- launch ----------------
extern "C" void kernel_launch(void* const* d_in, const int* in_sizes, int n_in,
                              void* d_out, int out_size)
{
    const float* det = (const float*)d_in[0];
    const float* seg = (const float*)d_in[1];
    const float* Wc  = (const float*)d_in[2];
    const float* bc  = (const float*)d_in[3];
    const float* Wfc = (const float*)d_in[4];
    const float* bfc = (const float*)d_in[5];
    const float* Ws  = (const float*)d_in[6];
    const float* bs  = (const float*)d_in[7];
    const float* Wr  = (const float*)d_in[8];
    const float* br  = (const float*)d_in[9];
    const float* Wi  = (const float*)d_in[10];
    const float* bi  = (const float*)d_in[11];
    const float* Wo  = (const float*)d_in[12];
    const float* bo  = (const float*)d_in[13];
    float* out = (float*)d_out;

    cudaFuncSetAttribute(convi_kernel, cudaFuncAttributeMaxDynamicSharedMemorySize,
                         SMEM_I_FLOATS * 4);
    cudaFuncSetAttribute(convo_kernel, cudaFuncAttributeMaxDynamicSharedMemorySize,
                         SMEM_O_FLOATS * 4);

    init_kernel<<<1, 256>>>();

    // detection head
    gemm_relu<1><<<dim3(8, 512), 256>>>(det, Wc, bc, g_x1, 72);    // 3x3 conv
    gemm_relu<0><<<dim3(8, 512), 256>>>(g_x1, Wfc, bfc, g_x2, 64); // 1x1 conv
    heads_kernel<<<8192, 256>>>(g_x2, Ws, bs, Wr, br);

    // top-2000 radix select + stable sort
    int shifts[4] = {24, 16, 8, 0};
    for (int p = 0; p < 4; p++) {
        rs_hist<<<256, 256>>>(shifts[p]);
        rs_scan<<<1, 1>>>(shifts[p]);
    }
    rs_gather<<<256, 256>>>();
    sort_kernel<<<1, 1024>>>();

    // NMS + top-500 selection (writes scores + decoded)
    nms_kernel<<<1, 1024>>>(out);

    // instance head
    convi_kernel<<<dim3(500, 3), 256, SMEM_I_FLOATS * 4>>>(seg, Wi, bi);
    convo_kernel<<<dim3(500, 6), 384, SMEM_O_FLOATS * 4>>>(Wo, bo, out);
}

// round 13
// speedup vs baseline: 3.7160x; 3.7160x over previous
#include <cuda_runtime.h>
#include <cuda_fp16.h>
#include <math.h>
#include <cstdint>

#define HD 256
#define WD 256
#define NPIX 65536
#define CD 128
#define FC 1024
#define HS 512
#define WSEG 512
#define CS 32
#define KTOP 2000
#define MAXOUT 500
#define CROP 48
#define CI 64
#define CAND_CAP 4096

#define OFF_SCORES 0
#define OFF_DEC 500
#define OFF_INST 1500
#define OFF_COORD 1153500

// ================= small PTX helpers (non-'a' target safe) =================
__device__ __forceinline__ uint32_t smem_to_u32(const void* p) {
    uint32_t a;
    asm("{ .reg .u64 t; cvta.to.shared.u64 t, %1; cvt.u32.u64 %0, t; }" : "=r"(a) : "l"(p));
    return a;
}
#define CP_ASYNC16(sdst, gsrc, szr) \
    asm volatile("cp.async.cg.shared.global [%0], [%1], 16, %2;" \
        :: "r"(sdst), "l"(gsrc), "r"(szr))
#define CP_COMMIT() asm volatile("cp.async.commit_group;" ::: "memory")
#define CP_WAIT1()  asm volatile("cp.async.wait_group 1;" ::: "memory")
#define CP_WAIT0()  asm volatile("cp.async.wait_group 0;" ::: "memory")
#define LDSM_X4(R0, R1, R2, R3, addr) \
    asm volatile("ldmatrix.sync.aligned.m8n8.x4.shared.b16 {%0,%1,%2,%3}, [%4];" \
        : "=r"(R0), "=r"(R1), "=r"(R2), "=r"(R3) : "r"(addr))
#define MMA16816(D, A, B0, B1) \
    asm volatile("mma.sync.aligned.m16n8k16.row.col.f32.f16.f16.f32 " \
        "{%0,%1,%2,%3}, {%4,%5,%6,%7}, {%8,%9}, {%0,%1,%2,%3};" \
        : "+f"((D)[0]), "+f"((D)[1]), "+f"((D)[2]), "+f"((D)[3]) \
        : "r"((A)[0]), "r"((A)[1]), "r"((A)[2]), "r"((A)[3]), "r"(B0), "r"(B1))

// ================= scratch =================
__device__ __align__(16) __half g_deth[(size_t)NPIX * CD];
__device__ __align__(16) __half g_detl[(size_t)NPIX * CD];
__device__ __align__(16) __half g_wt1h[(size_t)FC * 1152];
__device__ __align__(16) __half g_wt1l[(size_t)FC * 1152];
__device__ __align__(16) __half g_wt2h[(size_t)FC * FC];
__device__ __align__(16) __half g_wt2l[(size_t)FC * FC];
__device__ __align__(16) __half g_x1h[(size_t)NPIX * FC];
__device__ __align__(16) __half g_x1l[(size_t)NPIX * FC];
__device__ float g_x2[(size_t)NPIX * FC];
__device__ float g_logits[NPIX];
__device__ unsigned g_keys[NPIX];
__device__ float2 g_regv[NPIX];
__device__ unsigned g_counts[256];
__device__ unsigned g_prefix;
__device__ unsigned g_maskbits;
__device__ int g_want;
__device__ int g_ncand;
__device__ unsigned long long g_cand[CAND_CAP];
__device__ unsigned g_topidx[KTOP];
__device__ int g_start[MAXOUT * 2];
__device__ float g_h[(size_t)MAXOUT * CROP * CROP * CI];

// ================= init =================
__global__ void init_kernel() {
    int t = threadIdx.x;
    if (t < 256) g_counts[t] = 0;
    if (t == 0) { g_prefix = 0; g_maskbits = 0; g_want = KTOP; g_ncand = 0; }
    for (int i = t; i < CAND_CAP; i += blockDim.x) g_cand[i] = 0ull;
}

// ================= split prep =================
// features: x = h + l (l unscaled); weights: x = h + l/4096 (l scaled by 4096)
__global__ void split_det_kernel(const float* __restrict__ det) {
    size_t i = (size_t)blockIdx.x * blockDim.x + threadIdx.x;
    float x = det[i];
    __half h = __float2half(x);
    g_deth[i] = h;
    g_detl[i] = __float2half(x - __half2float(h));
}

// W [K][1024] fp32 -> out [1024][K] f16 hi/lo (transpose + split, weight scaling)
__global__ void split_wT_kernel(const float* __restrict__ W, __half* __restrict__ oh,
                                __half* __restrict__ ol, int K) {
    __shared__ float s[32][33];
    int k0 = blockIdx.x * 32, n0 = blockIdx.y * 32;
    int tx = threadIdx.x, ty = threadIdx.y;   // block (32, 8)
#pragma unroll
    for (int q = 0; q < 4; q++)
        s[ty + q * 8][tx] = W[(size_t)(k0 + ty + q * 8) * 1024 + n0 + tx];
    __syncthreads();
#pragma unroll
    for (int q = 0; q < 4; q++) {
        float x = s[tx][ty + q * 8];
        __half h = __float2half(x);
        __half l = __float2half((x - __half2float(h)) * 4096.f);
        size_t o = (size_t)(n0 + ty + q * 8) * K + k0 + tx;
        oh[o] = h; ol[o] = l;
    }
}

// ================= HMMA GEMM =================
// C[M,1024] = relu(A*B^T + bias). A = feat (h + l), B = weights (h + l/4096).
// accH += Ah*Bh + Al*Bh ; accM += Ah*Bl ; C = accH + accM/4096 + bias.
// CTA tile 128x128, 512 threads (16 warps, 4x4), warp tile 32x32, BK=32.
// smem row stride 80B (32 halves + 8 pad halves) -> ldmatrix conflict-free.
#define ASTRIDE 80
#define PLANE_BYTES (128 * ASTRIDE)      // 10240
#define BUF_BYTES (4 * PLANE_BYTES)      // Ah, Al, Bh, Bl
#define GSMEM_TOTAL (2 * BUF_BYTES)      // 81920

template <int IM2COL>
__global__ __launch_bounds__(512, 1) void gemm_tc(
    const __half* __restrict__ Ah, const __half* __restrict__ Al,
    const __half* __restrict__ Bh, const __half* __restrict__ Bl,
    const float* __restrict__ bias,
    float* __restrict__ Cf, __half* __restrict__ Ch, __half* __restrict__ Cl, int K)
{
    extern __shared__ char smem[];
    uint32_t sb = smem_to_u32(smem);
    int tid = threadIdx.x;
    int wid = tid >> 5, lane = tid & 31;
    int wm = wid & 3, wn = wid >> 2;
    int bx = blockIdx.x, by = blockIdx.y;
    int nb = bx * 128;
    int nch = K / 32;

    int y0 = 0, x0 = 0;
    if (IM2COL) { y0 = by >> 1; x0 = (by & 1) * 128; }

    float accH[2][4][4], accM[2][4][4];
#pragma unroll
    for (int mt = 0; mt < 2; mt++)
#pragma unroll
        for (int nt = 0; nt < 4; nt++)
#pragma unroll
            for (int i = 0; i < 4; i++) { accH[mt][nt][i] = 0.f; accM[mt][nt][i] = 0.f; }

    // ---- staging helper (executed by all 512 threads) ----
    auto stage = [&](int kt, int buf) {
        uint32_t base = sb + buf * BUF_BYTES;
        // A: 2 planes x 128 rows x 4 chunks of 16B = 1024 ops -> 2/thread
#pragma unroll
        for (int q = 0; q < 2; q++) {
            int idx = tid + q * 512;
            int plane = idx >> 9;
            int rem = idx & 511;
            int row = rem >> 2, ch = rem & 3;
            uint32_t sdst = base + plane * PLANE_BYTES + row * ASTRIDE + ch * 16;
            const __half* src;
            unsigned sz = 16;
            if (IM2COL) {
                int tap = kt >> 2;
                int c0 = (kt & 3) * 32 + ch * 8;
                int dy = tap / 3 - 1, dx = tap % 3 - 1;
                int yy = y0 + dy, xx = x0 + row + dx;
                bool valid = ((unsigned)yy < 256u) && ((unsigned)xx < 256u);
                size_t off = valid ? ((size_t)(yy * 256 + xx) * 128 + c0) : 0;
                sz = valid ? 16u : 0u;
                src = (plane ? Al : Ah) + off;
            } else {
                size_t off = (size_t)(by * 128 + row) * K + kt * 32 + ch * 8;
                src = (plane ? Al : Ah) + off;
            }
            CP_ASYNC16(sdst, src, sz);
        }
        // B: 2 planes x 128 rows x 4 chunks = 1024 ops -> 2/thread
#pragma unroll
        for (int q = 0; q < 2; q++) {
            int idx = tid + q * 512;
            int plane = idx >> 9;
            int rem = idx & 511;
            int row = rem >> 2, ch = rem & 3;
            uint32_t sdst = base + (2 + plane) * PLANE_BYTES + row * ASTRIDE + ch * 16;
            size_t off = (size_t)(nb + row) * K + kt * 32 + ch * 8;
            CP_ASYNC16(sdst, (plane ? Bl : Bh) + off, 16u);
        }
    };

    // ldmatrix per-lane address components
    int r8 = lane & 7;
    int a_rowoff = ((lane >> 3) & 1) * 8 + r8;
    int a_k16 = (lane >> 4) & 1;
    int b_rowoff = ((lane >> 4) & 1) * 8 + r8;
    int b_k16 = (lane >> 3) & 1;

    stage(0, 0);
    CP_COMMIT();

    for (int kt = 0; kt < nch; kt++) {
        if (kt + 1 < nch) { stage(kt + 1, (kt + 1) & 1); CP_COMMIT(); CP_WAIT1(); }
        else { CP_WAIT0(); }
        __syncthreads();

        uint32_t base = sb + (kt & 1) * BUF_BYTES;
#pragma unroll
        for (int ks = 0; ks < 2; ks++) {
            uint32_t ah[2][4], al[2][4], bh[4][2], bl[4][2];
#pragma unroll
            for (int mt = 0; mt < 2; mt++) {
                uint32_t aaddr = base + (wm * 32 + mt * 16 + a_rowoff) * ASTRIDE
                               + ks * 32 + a_k16 * 16;
                LDSM_X4(ah[mt][0], ah[mt][1], ah[mt][2], ah[mt][3], aaddr);
                LDSM_X4(al[mt][0], al[mt][1], al[mt][2], al[mt][3], aaddr + PLANE_BYTES);
            }
#pragma unroll
            for (int pr = 0; pr < 2; pr++) {
                uint32_t baddr = base + 2 * PLANE_BYTES
                               + (wn * 32 + pr * 16 + b_rowoff) * ASTRIDE
                               + ks * 32 + b_k16 * 16;
                uint32_t t0, t1, t2, t3;
                LDSM_X4(t0, t1, t2, t3, baddr);
                bh[2 * pr][0] = t0; bh[2 * pr][1] = t1;
                bh[2 * pr + 1][0] = t2; bh[2 * pr + 1][1] = t3;
                LDSM_X4(t0, t1, t2, t3, baddr + PLANE_BYTES);
                bl[2 * pr][0] = t0; bl[2 * pr][1] = t1;
                bl[2 * pr + 1][0] = t2; bl[2 * pr + 1][1] = t3;
            }
#pragma unroll
            for (int mt = 0; mt < 2; mt++)
#pragma unroll
                for (int nt = 0; nt < 4; nt++) {
                    MMA16816(accH[mt][nt], ah[mt], bh[nt][0], bh[nt][1]);
                    MMA16816(accH[mt][nt], al[mt], bh[nt][0], bh[nt][1]);
                    MMA16816(accM[mt][nt], ah[mt], bl[nt][0], bl[nt][1]);
                }
        }
        __syncthreads();
    }

    // ---- epilogue ----
    int g = lane >> 2, tig = lane & 3;
#pragma unroll
    for (int mt = 0; mt < 2; mt++) {
#pragma unroll
        for (int rh = 0; rh < 2; rh++) {
            int mloc = wm * 32 + mt * 16 + g + rh * 8;
            size_t mg = (size_t)(by * 128 + mloc);
#pragma unroll
            for (int nt = 0; nt < 4; nt++) {
                int ncol = nb + wn * 32 + nt * 8 + 2 * tig;
                float d0 = accH[mt][nt][rh * 2 + 0] + accM[mt][nt][rh * 2 + 0] * (1.f / 4096.f);
                float d1 = accH[mt][nt][rh * 2 + 1] + accM[mt][nt][rh * 2 + 1] * (1.f / 4096.f);
                d0 = fmaxf(d0 + bias[ncol], 0.f);
                d1 = fmaxf(d1 + bias[ncol + 1], 0.f);
                if (IM2COL) {
                    __half h0 = __float2half(d0), h1 = __float2half(d1);
                    __half l0 = __float2half(d0 - __half2float(h0));
                    __half l1 = __float2half(d1 - __half2float(h1));
                    *(__half2*)&Ch[mg * 1024 + ncol] = __halves2half2(h0, h1);
                    *(__half2*)&Cl[mg * 1024 + ncol] = __halves2half2(l0, l1);
                } else {
                    *(float2*)&Cf[mg * 1024 + ncol] = make_float2(d0, d1);
                }
            }
        }
    }
}

// ================= heads =================
__global__ void heads_kernel(const float* __restrict__ x2,
                             const float* __restrict__ Ws, const float* __restrict__ bs,
                             const float* __restrict__ Wr, const float* __restrict__ br)
{
    int gid = blockIdx.x * blockDim.x + threadIdx.x;
    int m = gid >> 5;
    int lane = threadIdx.x & 31;
    if (m >= NPIX) return;
    const float* xr = x2 + (size_t)m * 1024;
    float s = 0.f, r0 = 0.f, r1 = 0.f;
    for (int c = lane; c < 1024; c += 32) {
        float x = xr[c];
        s += x * Ws[c];
        r0 += x * Wr[2 * c];
        r1 += x * Wr[2 * c + 1];
    }
#pragma unroll
    for (int o = 16; o; o >>= 1) {
        s  += __shfl_down_sync(0xFFFFFFFFu, s, o);
        r0 += __shfl_down_sync(0xFFFFFFFFu, r0, o);
        r1 += __shfl_down_sync(0xFFFFFFFFu, r1, o);
    }
    if (lane == 0) {
        float logit = s + bs[0];
        g_logits[m] = logit;
        unsigned b = __float_as_uint(logit);
        g_keys[m] = (b & 0x80000000u) ? ~b : (b | 0x80000000u);
        g_regv[m] = make_float2(r0 + br[0], r1 + br[1]);
    }
}

// ================= radix select =================
__global__ void rs_hist(int shift) {
    __shared__ unsigned hc[256];
    int t = threadIdx.x;
    hc[t] = 0;
    __syncthreads();
    int m = blockIdx.x * 256 + t;
    unsigned key = g_keys[m];
    if ((key & g_maskbits) == g_prefix)
        atomicAdd(&hc[(key >> shift) & 0xFFu], 1u);
    __syncthreads();
    if (hc[t]) atomicAdd(&g_counts[t], hc[t]);
}

__global__ void rs_scan(int shift) {
    int want = g_want;
    unsigned cum = 0;
    int sel = 0;
    for (int b = 255; b >= 0; b--) {
        unsigned c = g_counts[b];
        if (cum + c >= (unsigned)want) { sel = b; g_want = want - (int)cum; break; }
        cum += c;
    }
    g_prefix |= ((unsigned)sel) << shift;
    g_maskbits |= 0xFFu << shift;
    for (int b = 0; b < 256; b++) g_counts[b] = 0;
}

__global__ void rs_gather() {
    int m = blockIdx.x * 256 + threadIdx.x;
    unsigned key = g_keys[m];
    if (key >= g_prefix) {
        int p = atomicAdd(&g_ncand, 1);
        if (p < CAND_CAP)
            g_cand[p] = ((unsigned long long)key << 32) | (unsigned)(~m);
    }
}

// ================= bitonic sort =================
__global__ void sort_kernel() {
    __shared__ unsigned long long s[CAND_CAP];
    int tid = threadIdx.x;
    for (int i = tid; i < CAND_CAP; i += 1024) s[i] = g_cand[i];
    __syncthreads();
    for (int k = 2; k <= CAND_CAP; k <<= 1) {
        for (int j = k >> 1; j > 0; j >>= 1) {
#pragma unroll
            for (int q = 0; q < 4; q++) {
                int t = tid + q * 1024;
                int ixj = t ^ j;
                if (ixj > t) {
                    unsigned long long a = s[t], b = s[ixj];
                    bool seg = (t & k) == 0;
                    if (seg ? (a < b) : (a > b)) { s[t] = b; s[ixj] = a; }
                }
            }
            __syncthreads();
        }
    }
    for (int i = tid; i < KTOP; i += 1024)
        g_topidx[i] = ~((unsigned)(s[i] & 0xFFFFFFFFull));
}

// ================= NMS + top-500 =================
__global__ void nms_kernel(float* __restrict__ d_out) {
    __shared__ float sy[KTOP], sx[KTOP], slog[KTOP];
    __shared__ unsigned char supp[KTOP];
    __shared__ int sel[MAXOUT];
    __shared__ float selsc[MAXOUT];
    int tid = threadIdx.x;
    for (int i = tid; i < KTOP; i += 1024) {
        unsigned idx = g_topidx[i];
        int y = idx >> 8;
        int x = idx & 255;
        float2 r = g_regv[idx];
        sy[i] = (float)y + 0.5f + r.x;
        sx[i] = (float)x + 0.5f + r.y;
        slog[i] = g_logits[idx];
        supp[i] = 0;
    }
    __syncthreads();
    for (int i = 0; i < KTOP; i++) {
        if (!supp[i]) {
            float by = sy[i], bx = sx[i];
#pragma unroll
            for (int q = 0; q < 2; q++) {
                int j = tid + q * 1024;
                if (j > i && j < KTOP && !supp[j]) {
                    float dy = sy[j] - by;
                    float dx = sx[j] - bx;
                    if (dy * dy + dx * dx < 1.0f) supp[j] = 1;
                }
            }
        }
        __syncthreads();
    }
    if (tid == 0) {
        int c = 0;
        for (int i = 0; i < KTOP && c < MAXOUT; i++)
            if (!supp[i]) { sel[c] = i; selsc[c] = 1.f / (1.f + expf(-slog[i])); c++; }
        for (int i = 0; i < KTOP && c < MAXOUT; i++)
            if (supp[i]) { sel[c] = i; selsc[c] = -1.f; c++; }
    }
    __syncthreads();
    if (tid < MAXOUT) {
        int i = sel[tid];
        d_out[OFF_SCORES + tid] = selsc[tid];
        d_out[OFF_DEC + 2 * tid] = sy[i] * 4.f;
        d_out[OFF_DEC + 2 * tid + 1] = sx[i] * 4.f;
        float ry = rintf(sy[i] * 2.f - 24.f);
        float rx = rintf(sx[i] * 2.f - 24.f);
        int syi = (int)fminf(fmaxf(ry, 0.f), (float)(HS - CROP));
        int sxi = (int)fminf(fmaxf(rx, 0.f), (float)(WSEG - CROP));
        g_start[2 * tid] = syi;
        g_start[2 * tid + 1] = sxi;
    }
}

// ================= instance conv1 =================
#define SMEM_I_FLOATS (18 * 50 * 33 + 288 * 64)
__global__ __launch_bounds__(256) void convi_kernel(
    const float* __restrict__ seg, const float* __restrict__ Wi, const float* __restrict__ bi)
{
    extern __shared__ float sm[];
    float* in_s = sm;
    float* ws = sm + 18 * 50 * 33;

    int crop = blockIdx.x;
    int strip = blockIdx.y;
    int tid = threadIdx.x;

    int sy = g_start[2 * crop], sx = g_start[2 * crop + 1];

    for (int id = tid; id < 288 * 64; id += 256) ws[id] = Wi[id];

    int r0 = strip * 16 - 1;
    for (int id = tid; id < 18 * 50 * 32; id += 256) {
        int ci = id & 31;
        int rest = id >> 5;
        int cc = rest % 50;
        int rr = rest / 50;
        int rin = r0 + rr;
        int cin = cc - 1;
        float v = 0.f;
        if ((unsigned)rin < 48u && (unsigned)cin < 48u)
            v = seg[((size_t)(sy + rin) * 512 + (sx + cin)) * 32 + ci];
        in_s[(rr * 50 + cc) * 33 + ci] = v;
    }
    __syncthreads();

    int r = tid >> 4;
    int cg = tid & 15;
    int c0 = cg * 3;
    int r_out = strip * 16 + r;

    for (int cog = 0; cog < 4; cog++) {
        float acc[48];
#pragma unroll
        for (int i = 0; i < 48; i++) acc[i] = 0.f;
#pragma unroll
        for (int dy = 0; dy < 3; dy++) {
#pragma unroll
            for (int dx = 0; dx < 3; dx++) {
                const float* wbase = ws + ((dy * 3 + dx) * 32) * 64 + cog * 16;
                const float* ibase = in_s + ((r + dy) * 50 + (c0 + dx)) * 33;
#pragma unroll 4
                for (int ci = 0; ci < 32; ci++) {
                    float4 w0 = *(const float4*)(wbase + ci * 64);
                    float4 w1 = *(const float4*)(wbase + ci * 64 + 4);
                    float4 w2 = *(const float4*)(wbase + ci * 64 + 8);
                    float4 w3 = *(const float4*)(wbase + ci * 64 + 12);
                    float wv[16] = {w0.x, w0.y, w0.z, w0.w, w1.x, w1.y, w1.z, w1.w,
                                    w2.x, w2.y, w2.z, w2.w, w3.x, w3.y, w3.z, w3.w};
                    float v0 = ibase[ci];
                    float v1 = ibase[33 + ci];
                    float v2 = ibase[66 + ci];
#pragma unroll
                    for (int co = 0; co < 16; co++) {
                        acc[co] += v0 * wv[co];
                        acc[16 + co] += v1 * wv[co];
                        acc[32 + co] += v2 * wv[co];
                    }
                }
            }
        }
#pragma unroll
        for (int col = 0; col < 3; col++) {
            int c = c0 + col;
            float* dst = g_h + (((size_t)crop * 48 + r_out) * 48 + c) * 64 + cog * 16;
#pragma unroll
            for (int j = 0; j < 16; j += 4) {
                float4 o;
                o.x = fmaxf(acc[col * 16 + j + 0] + bi[cog * 16 + j + 0], 0.f);
                o.y = fmaxf(acc[col * 16 + j + 1] + bi[cog * 16 + j + 1], 0.f);
                o.z = fmaxf(acc[col * 16 + j + 2] + bi[cog * 16 + j + 2], 0.f);
                o.w = fmaxf(acc[col * 16 + j + 3] + bi[cog * 16 + j + 3], 0.f);
                *(float4*)(dst + j) = o;
            }
        }
    }
}

// ================= instance conv2 =================
#define SMEM_O_FLOATS (10 * 48 * 65 + 576)
__global__ __launch_bounds__(384) void convo_kernel(
    const float* __restrict__ Wo, const float* __restrict__ bo, float* __restrict__ d_out)
{
    extern __shared__ float sm[];
    float* h_s = sm;
    float* wsm = sm + 10 * 48 * 65;

    int crop = blockIdx.x;
    int strip = blockIdx.y;
    int tid = threadIdx.x;

    for (int i = tid; i < 576; i += 384) wsm[i] = Wo[i];

    int r0 = strip * 8 - 1;
    for (int id = tid; id < 10 * 48 * 64; id += 384) {
        int co = id & 63;
        int rest = id >> 6;
        int cc = rest % 48;
        int rr = rest / 48;
        int rin = r0 + rr;
        float v = 0.f;
        if ((unsigned)rin < 48u)
            v = g_h[(((size_t)crop * 48 + rin) * 48 + cc) * 64 + co];
        h_s[(rr * 48 + cc) * 65 + co] = v;
    }
    __syncthreads();

    int r = tid / 48;
    int c = tid % 48;
    float acc = bo[0];
#pragma unroll
    for (int dy = 0; dy < 3; dy++) {
#pragma unroll
        for (int dx = 0; dx < 3; dx++) {
            int hc = c + dx - 1;
            if ((unsigned)hc < 48u) {
                const float* hb = h_s + ((r + dy) * 48 + hc) * 65;
                const float* wb = wsm + (dy * 3 + dx) * 64;
#pragma unroll 8
                for (int ci = 0; ci < 64; ci++) acc += hb[ci] * wb[ci];
            }
        }
    }
    float o = 1.f / (1.f + expf(-acc));
    int r_out = strip * 8 + r;
    size_t oi = ((size_t)crop * 48 + r_out) * 48 + c;
    d_out[OFF_INST + oi] = o;
    int syi = g_start[2 * crop], sxi = g_start[2 * crop + 1];
    d_out[OFF_COORD + oi * 2] = (float)(syi + r_out);
    d_out[OFF_COORD + oi * 2 + 1] = (float)(sxi + c);
}

// ================= launch =================
extern "C" void kernel_launch(void* const* d_in, const int* in_sizes, int n_in,
                              void* d_out, int out_size)
{
    const float* det = (const float*)d_in[0];
    const float* seg = (const float*)d_in[1];
    const float* Wc  = (const float*)d_in[2];
    const float* bc  = (const float*)d_in[3];
    const float* Wfc = (const float*)d_in[4];
    const float* bfc = (const float*)d_in[5];
    const float* Ws  = (const float*)d_in[6];
    const float* bs  = (const float*)d_in[7];
    const float* Wr  = (const float*)d_in[8];
    const float* br  = (const float*)d_in[9];
    const float* Wi  = (const float*)d_in[10];
    const float* bi  = (const float*)d_in[11];
    const float* Wo  = (const float*)d_in[12];
    const float* bo  = (const float*)d_in[13];
    float* out = (float*)d_out;

    __half *p_deth, *p_detl, *p_wt1h, *p_wt1l, *p_wt2h, *p_wt2l, *p_x1h, *p_x1l;
    cudaGetSymbolAddress((void**)&p_deth, g_deth);
    cudaGetSymbolAddress((void**)&p_detl, g_detl);
    cudaGetSymbolAddress((void**)&p_wt1h, g_wt1h);
    cudaGetSymbolAddress((void**)&p_wt1l, g_wt1l);
    cudaGetSymbolAddress((void**)&p_wt2h, g_wt2h);
    cudaGetSymbolAddress((void**)&p_wt2l, g_wt2l);
    cudaGetSymbolAddress((void**)&p_x1h, g_x1h);
    cudaGetSymbolAddress((void**)&p_x1l, g_x1l);
    float* p_x2;
    cudaGetSymbolAddress((void**)&p_x2, g_x2);

    cudaFuncSetAttribute(gemm_tc<1>, cudaFuncAttributeMaxDynamicSharedMemorySize, GSMEM_TOTAL);
    cudaFuncSetAttribute(gemm_tc<0>, cudaFuncAttributeMaxDynamicSharedMemorySize, GSMEM_TOTAL);
    cudaFuncSetAttribute(convi_kernel, cudaFuncAttributeMaxDynamicSharedMemorySize,
                         SMEM_I_FLOATS * 4);
    cudaFuncSetAttribute(convo_kernel, cudaFuncAttributeMaxDynamicSharedMemorySize,
                         SMEM_O_FLOATS * 4);

    init_kernel<<<1, 256>>>();

    // prep: split/transpose
    split_det_kernel<<<(NPIX * CD) / 512, 512>>>(det);
    split_wT_kernel<<<dim3(36, 32), dim3(32, 8)>>>(Wc, p_wt1h, p_wt1l, 1152);
    split_wT_kernel<<<dim3(32, 32), dim3(32, 8)>>>(Wfc, p_wt2h, p_wt2l, 1024);

    // detection head (HMMA tensor path)
    gemm_tc<1><<<dim3(8, 512), 512, GSMEM_TOTAL>>>(
        p_deth, p_detl, p_wt1h, p_wt1l, bc, nullptr, p_x1h, p_x1l, 1152);
    gemm_tc<0><<<dim3(8, 512), 512, GSMEM_TOTAL>>>(
        p_x1h, p_x1l, p_wt2h, p_wt2l, bfc, p_x2, nullptr, nullptr, 1024);

    heads_kernel<<<8192, 256>>>(p_x2, Ws, bs, Wr, br);

    // top-2000 radix select + stable sort
    int shifts[4] = {24, 16, 8, 0};
    for (int p = 0; p < 4; p++) {
        rs_hist<<<256, 256>>>(shifts[p]);
        rs_scan<<<1, 1>>>(shifts[p]);
    }
    rs_gather<<<256, 256>>>();
    sort_kernel<<<1, 1024>>>();

    nms_kernel<<<1, 1024>>>(out);

    // instance head
    convi_kernel<<<dim3(500, 3), 256, SMEM_I_FLOATS * 4>>>(seg, Wi, bi);
    convo_kernel<<<dim3(500, 6), 384, SMEM_O_FLOATS * 4>>>(Wo, bo, out);
}

// round 15
// speedup vs baseline: 4.4536x; 1.1985x over previous
#include <cuda_runtime.h>
#include <cuda_fp16.h>
#include <math.h>
#include <cstdint>

#define HD 256
#define WD 256
#define NPIX 65536
#define CD 128
#define FC 1024
#define HS 512
#define WSEG 512
#define CS 32
#define KTOP 2000
#define MAXOUT 500
#define CROP 48
#define CI 64
#define CAND_CAP 4096

#define OFF_SCORES 0
#define OFF_DEC 500
#define OFF_INST 1500
#define OFF_COORD 1153500

// ================= small PTX helpers (non-'a' target safe) =================
__device__ __forceinline__ uint32_t smem_to_u32(const void* p) {
    uint32_t a;
    asm("{ .reg .u64 t; cvta.to.shared.u64 t, %1; cvt.u32.u64 %0, t; }" : "=r"(a) : "l"(p));
    return a;
}
#define CP_ASYNC16(sdst, gsrc, szr) \
    asm volatile("cp.async.cg.shared.global [%0], [%1], 16, %2;" \
        :: "r"(sdst), "l"(gsrc), "r"(szr))
#define CP_COMMIT() asm volatile("cp.async.commit_group;" ::: "memory")
#define CP_WAIT1()  asm volatile("cp.async.wait_group 1;" ::: "memory")
#define CP_WAIT0()  asm volatile("cp.async.wait_group 0;" ::: "memory")
#define LDSM_X4(R0, R1, R2, R3, addr) \
    asm volatile("ldmatrix.sync.aligned.m8n8.x4.shared.b16 {%0,%1,%2,%3}, [%4];" \
        : "=r"(R0), "=r"(R1), "=r"(R2), "=r"(R3) : "r"(addr))
#define MMA16816(D, A, B0, B1) \
    asm volatile("mma.sync.aligned.m16n8k16.row.col.f32.f16.f16.f32 " \
        "{%0,%1,%2,%3}, {%4,%5,%6,%7}, {%8,%9}, {%0,%1,%2,%3};" \
        : "+f"((D)[0]), "+f"((D)[1]), "+f"((D)[2]), "+f"((D)[3]) \
        : "r"((A)[0]), "r"((A)[1]), "r"((A)[2]), "r"((A)[3]), "r"(B0), "r"(B1))

// ================= scratch =================
__device__ __align__(16) __half g_deth[(size_t)NPIX * CD];
__device__ __align__(16) __half g_detl[(size_t)NPIX * CD];
__device__ __align__(16) __half g_wt1h[(size_t)FC * 1152];
__device__ __align__(16) __half g_wt1l[(size_t)FC * 1152];
__device__ __align__(16) __half g_wt2h[(size_t)FC * FC];
__device__ __align__(16) __half g_wt2l[(size_t)FC * FC];
__device__ __align__(16) __half g_x1h[(size_t)NPIX * FC];
__device__ __align__(16) __half g_x1l[(size_t)NPIX * FC];
__device__ float g_x2[(size_t)NPIX * FC];
__device__ __align__(16) __half g_segh[(size_t)HS * WSEG * CS];
__device__ __align__(16) __half g_wiT[64 * 288];
__device__ float g_logits[NPIX];
__device__ unsigned g_keys[NPIX];
__device__ float2 g_regv[NPIX];
__device__ unsigned g_counts[256];
__device__ unsigned g_prefix;
__device__ unsigned g_maskbits;
__device__ int g_want;
__device__ int g_ncand;
__device__ unsigned long long g_cand[CAND_CAP];
__device__ unsigned g_topidx[KTOP];
__device__ int g_start[MAXOUT * 2];
__device__ __align__(16) __half g_h[(size_t)MAXOUT * CROP * CROP * CI];  // f16 now

// ================= init =================
__global__ void init_kernel() {
    int t = threadIdx.x;
    if (t < 256) g_counts[t] = 0;
    if (t == 0) { g_prefix = 0; g_maskbits = 0; g_want = KTOP; g_ncand = 0; }
    for (int i = t; i < CAND_CAP; i += blockDim.x) g_cand[i] = 0ull;
}

// ================= split prep =================
__global__ void split_det_kernel(const float* __restrict__ det) {
    size_t i = (size_t)blockIdx.x * blockDim.x + threadIdx.x;
    float x = det[i];
    __half h = __float2half(x);
    g_deth[i] = h;
    g_detl[i] = __float2half(x - __half2float(h));
}

__global__ void split_seg_kernel(const float* __restrict__ seg) {
    size_t i = (size_t)blockIdx.x * blockDim.x + threadIdx.x;
    g_segh[i] = __float2half(seg[i]);
}

// Wi [288][64] fp32 -> WiT f16 [64][288]
__global__ void prep_wiT_kernel(const float* __restrict__ Wi) {
    for (int i = threadIdx.x; i < 64 * 288; i += blockDim.x) {
        int co = i / 288, k = i % 288;
        g_wiT[co * 288 + k] = __float2half(Wi[k * 64 + co]);
    }
}

// W [K][1024] fp32 -> out [1024][K] f16 hi/lo (transpose + split, weight scaling)
__global__ void split_wT_kernel(const float* __restrict__ W, __half* __restrict__ oh,
                                __half* __restrict__ ol, int K) {
    __shared__ float s[32][33];
    int k0 = blockIdx.x * 32, n0 = blockIdx.y * 32;
    int tx = threadIdx.x, ty = threadIdx.y;   // block (32, 8)
#pragma unroll
    for (int q = 0; q < 4; q++)
        s[ty + q * 8][tx] = W[(size_t)(k0 + ty + q * 8) * 1024 + n0 + tx];
    __syncthreads();
#pragma unroll
    for (int q = 0; q < 4; q++) {
        float x = s[tx][ty + q * 8];
        __half h = __float2half(x);
        __half l = __float2half((x - __half2float(h)) * 4096.f);
        size_t o = (size_t)(n0 + ty + q * 8) * K + k0 + tx;
        oh[o] = h; ol[o] = l;
    }
}

// ================= HMMA GEMM (detection) =================
// CTA 128x128, 256 threads (8 warps, 2m x 4n), warp tile 64x32, BK=32.
#define ASTRIDE 80
#define PLANE_BYTES (128 * ASTRIDE)
#define BUF_BYTES (4 * PLANE_BYTES)
#define GSMEM_TOTAL (2 * BUF_BYTES)

template <int IM2COL>
__global__ __launch_bounds__(256, 1) void gemm_tc(
    const __half* __restrict__ Ah, const __half* __restrict__ Al,
    const __half* __restrict__ Bh, const __half* __restrict__ Bl,
    const float* __restrict__ bias,
    float* __restrict__ Cf, __half* __restrict__ Ch, __half* __restrict__ Cl, int K)
{
    extern __shared__ char smem[];
    uint32_t sb = smem_to_u32(smem);
    int tid = threadIdx.x;
    int wid = tid >> 5, lane = tid & 31;
    int wm = wid & 1, wn = wid >> 1;        // 2 m-warps x 4 n-warps
    int bx = blockIdx.x, by = blockIdx.y;
    int nb = bx * 128;
    int nch = K / 32;

    int y0 = 0, x0 = 0;
    if (IM2COL) { y0 = by >> 1; x0 = (by & 1) * 128; }

    float accH[4][4][4], accM[4][4][4];
#pragma unroll
    for (int mt = 0; mt < 4; mt++)
#pragma unroll
        for (int nt = 0; nt < 4; nt++)
#pragma unroll
            for (int i = 0; i < 4; i++) { accH[mt][nt][i] = 0.f; accM[mt][nt][i] = 0.f; }

    auto stage = [&](int kt, int buf) {
        uint32_t base = sb + buf * BUF_BYTES;
#pragma unroll
        for (int q = 0; q < 4; q++) {
            int idx = tid + q * 256;
            int plane = idx >> 9;
            int rem = idx & 511;
            int row = rem >> 2, ch = rem & 3;
            uint32_t sdst = base + plane * PLANE_BYTES + row * ASTRIDE + ch * 16;
            const __half* src;
            unsigned sz = 16;
            if (IM2COL) {
                int tap = kt >> 2;
                int c0 = (kt & 3) * 32 + ch * 8;
                int dy = tap / 3 - 1, dx = tap % 3 - 1;
                int yy = y0 + dy, xx = x0 + row + dx;
                bool valid = ((unsigned)yy < 256u) && ((unsigned)xx < 256u);
                size_t off = valid ? ((size_t)(yy * 256 + xx) * 128 + c0) : 0;
                sz = valid ? 16u : 0u;
                src = (plane ? Al : Ah) + off;
            } else {
                size_t off = (size_t)(by * 128 + row) * K + kt * 32 + ch * 8;
                src = (plane ? Al : Ah) + off;
            }
            CP_ASYNC16(sdst, src, sz);
        }
#pragma unroll
        for (int q = 0; q < 4; q++) {
            int idx = tid + q * 256;
            int plane = idx >> 9;
            int rem = idx & 511;
            int row = rem >> 2, ch = rem & 3;
            uint32_t sdst = base + (2 + plane) * PLANE_BYTES + row * ASTRIDE + ch * 16;
            size_t off = (size_t)(nb + row) * K + kt * 32 + ch * 8;
            CP_ASYNC16(sdst, (plane ? Bl : Bh) + off, 16u);
        }
    };

    int r8 = lane & 7;
    int a_rowoff = ((lane >> 3) & 1) * 8 + r8;
    int a_k16 = (lane >> 4) & 1;
    int b_rowoff = ((lane >> 4) & 1) * 8 + r8;
    int b_k16 = (lane >> 3) & 1;

    stage(0, 0);
    CP_COMMIT();

    for (int kt = 0; kt < nch; kt++) {
        if (kt + 1 < nch) { stage(kt + 1, (kt + 1) & 1); CP_COMMIT(); CP_WAIT1(); }
        else { CP_WAIT0(); }
        __syncthreads();

        uint32_t base = sb + (kt & 1) * BUF_BYTES;
#pragma unroll
        for (int ks = 0; ks < 2; ks++) {
            uint32_t ah[4][4], al[4][4], bh[4][2], bl[4][2];
#pragma unroll
            for (int mt = 0; mt < 4; mt++) {
                uint32_t aaddr = base + (wm * 64 + mt * 16 + a_rowoff) * ASTRIDE
                               + ks * 32 + a_k16 * 16;
                LDSM_X4(ah[mt][0], ah[mt][1], ah[mt][2], ah[mt][3], aaddr);
                LDSM_X4(al[mt][0], al[mt][1], al[mt][2], al[mt][3], aaddr + PLANE_BYTES);
            }
#pragma unroll
            for (int pr = 0; pr < 2; pr++) {
                uint32_t baddr = base + 2 * PLANE_BYTES
                               + (wn * 32 + pr * 16 + b_rowoff) * ASTRIDE
                               + ks * 32 + b_k16 * 16;
                uint32_t t0, t1, t2, t3;
                LDSM_X4(t0, t1, t2, t3, baddr);
                bh[2 * pr][0] = t0; bh[2 * pr][1] = t1;
                bh[2 * pr + 1][0] = t2; bh[2 * pr + 1][1] = t3;
                LDSM_X4(t0, t1, t2, t3, baddr + PLANE_BYTES);
                bl[2 * pr][0] = t0; bl[2 * pr][1] = t1;
                bl[2 * pr + 1][0] = t2; bl[2 * pr + 1][1] = t3;
            }
#pragma unroll
            for (int mt = 0; mt < 4; mt++)
#pragma unroll
                for (int nt = 0; nt < 4; nt++) {
                    MMA16816(accH[mt][nt], ah[mt], bh[nt][0], bh[nt][1]);
                    MMA16816(accH[mt][nt], al[mt], bh[nt][0], bh[nt][1]);
                    MMA16816(accM[mt][nt], ah[mt], bl[nt][0], bl[nt][1]);
                }
        }
        __syncthreads();
    }

    int g = lane >> 2, tig = lane & 3;
#pragma unroll
    for (int mt = 0; mt < 4; mt++) {
#pragma unroll
        for (int rh = 0; rh < 2; rh++) {
            int mloc = wm * 64 + mt * 16 + g + rh * 8;
            size_t mg = (size_t)(by * 128 + mloc);
#pragma unroll
            for (int nt = 0; nt < 4; nt++) {
                int ncol = nb + wn * 32 + nt * 8 + 2 * tig;
                float d0 = accH[mt][nt][rh * 2 + 0] + accM[mt][nt][rh * 2 + 0] * (1.f / 4096.f);
                float d1 = accH[mt][nt][rh * 2 + 1] + accM[mt][nt][rh * 2 + 1] * (1.f / 4096.f);
                d0 = fmaxf(d0 + bias[ncol], 0.f);
                d1 = fmaxf(d1 + bias[ncol + 1], 0.f);
                if (IM2COL) {
                    __half h0 = __float2half(d0), h1 = __float2half(d1);
                    __half l0 = __float2half(d0 - __half2float(h0));
                    __half l1 = __float2half(d1 - __half2float(h1));
                    *(__half2*)&Ch[mg * 1024 + ncol] = __halves2half2(h0, h1);
                    *(__half2*)&Cl[mg * 1024 + ncol] = __halves2half2(l0, l1);
                } else {
                    *(float2*)&Cf[mg * 1024 + ncol] = make_float2(d0, d1);
                }
            }
        }
    }
}

// ================= heads =================
__global__ void heads_kernel(const float* __restrict__ x2,
                             const float* __restrict__ Ws, const float* __restrict__ bs,
                             const float* __restrict__ Wr, const float* __restrict__ br)
{
    int gid = blockIdx.x * blockDim.x + threadIdx.x;
    int m = gid >> 5;
    int lane = threadIdx.x & 31;
    if (m >= NPIX) return;
    const float* xr = x2 + (size_t)m * 1024;
    float s = 0.f, r0 = 0.f, r1 = 0.f;
    for (int c = lane; c < 1024; c += 32) {
        float x = xr[c];
        s += x * Ws[c];
        r0 += x * Wr[2 * c];
        r1 += x * Wr[2 * c + 1];
    }
#pragma unroll
    for (int o = 16; o; o >>= 1) {
        s  += __shfl_down_sync(0xFFFFFFFFu, s, o);
        r0 += __shfl_down_sync(0xFFFFFFFFu, r0, o);
        r1 += __shfl_down_sync(0xFFFFFFFFu, r1, o);
    }
    if (lane == 0) {
        float logit = s + bs[0];
        g_logits[m] = logit;
        unsigned b = __float_as_uint(logit);
        g_keys[m] = (b & 0x80000000u) ? ~b : (b | 0x80000000u);
        g_regv[m] = make_float2(r0 + br[0], r1 + br[1]);
    }
}

// ================= radix select =================
__global__ void rs_hist(int shift) {
    __shared__ unsigned hc[256];
    int t = threadIdx.x;
    hc[t] = 0;
    __syncthreads();
    int m = blockIdx.x * 256 + t;
    unsigned key = g_keys[m];
    if ((key & g_maskbits) == g_prefix)
        atomicAdd(&hc[(key >> shift) & 0xFFu], 1u);
    __syncthreads();
    if (hc[t]) atomicAdd(&g_counts[t], hc[t]);
}

__global__ void rs_scan(int shift) {
    int want = g_want;
    unsigned cum = 0;
    int sel = 0;
    for (int b = 255; b >= 0; b--) {
        unsigned c = g_counts[b];
        if (cum + c >= (unsigned)want) { sel = b; g_want = want - (int)cum; break; }
        cum += c;
    }
    g_prefix |= ((unsigned)sel) << shift;
    g_maskbits |= 0xFFu << shift;
    for (int b = 0; b < 256; b++) g_counts[b] = 0;
}

__global__ void rs_gather() {
    int m = blockIdx.x * 256 + threadIdx.x;
    unsigned key = g_keys[m];
    if (key >= g_prefix) {
        int p = atomicAdd(&g_ncand, 1);
        if (p < CAND_CAP)
            g_cand[p] = ((unsigned long long)key << 32) | (unsigned)(~m);
    }
}

// ================= bitonic sort =================
__global__ void sort_kernel() {
    __shared__ unsigned long long s[CAND_CAP];
    int tid = threadIdx.x;
    for (int i = tid; i < CAND_CAP; i += 1024) s[i] = g_cand[i];
    __syncthreads();
    for (int k = 2; k <= CAND_CAP; k <<= 1) {
        for (int j = k >> 1; j > 0; j >>= 1) {
#pragma unroll
            for (int q = 0; q < 4; q++) {
                int t = tid + q * 1024;
                int ixj = t ^ j;
                if (ixj > t) {
                    unsigned long long a = s[t], b = s[ixj];
                    bool seg = (t & k) == 0;
                    if (seg ? (a < b) : (a > b)) { s[t] = b; s[ixj] = a; }
                }
            }
            __syncthreads();
        }
    }
    for (int i = tid; i < KTOP; i += 1024)
        g_topidx[i] = ~((unsigned)(s[i] & 0xFFFFFFFFull));
}

// ================= NMS + top-500 =================
__global__ void nms_kernel(float* __restrict__ d_out) {
    __shared__ float sy[KTOP], sx[KTOP], slog[KTOP];
    __shared__ unsigned char supp[KTOP];
    __shared__ int sel[MAXOUT];
    __shared__ float selsc[MAXOUT];
    int tid = threadIdx.x;
    for (int i = tid; i < KTOP; i += 1024) {
        unsigned idx = g_topidx[i];
        int y = idx >> 8;
        int x = idx & 255;
        float2 r = g_regv[idx];
        sy[i] = (float)y + 0.5f + r.x;
        sx[i] = (float)x + 0.5f + r.y;
        slog[i] = g_logits[idx];
        supp[i] = 0;
    }
    __syncthreads();
    for (int i = 0; i < KTOP; i++) {
        if (!supp[i]) {
            float by = sy[i], bx = sx[i];
#pragma unroll
            for (int q = 0; q < 2; q++) {
                int j = tid + q * 1024;
                if (j > i && j < KTOP && !supp[j]) {
                    float dy = sy[j] - by;
                    float dx = sx[j] - bx;
                    if (dy * dy + dx * dx < 1.0f) supp[j] = 1;
                }
            }
        }
        __syncthreads();
    }
    if (tid == 0) {
        int c = 0;
        for (int i = 0; i < KTOP && c < MAXOUT; i++)
            if (!supp[i]) { sel[c] = i; selsc[c] = 1.f / (1.f + expf(-slog[i])); c++; }
        for (int i = 0; i < KTOP && c < MAXOUT; i++)
            if (supp[i]) { sel[c] = i; selsc[c] = -1.f; c++; }
    }
    __syncthreads();
    if (tid < MAXOUT) {
        int i = sel[tid];
        d_out[OFF_SCORES + tid] = selsc[tid];
        d_out[OFF_DEC + 2 * tid] = sy[i] * 4.f;
        d_out[OFF_DEC + 2 * tid + 1] = sx[i] * 4.f;
        float ry = rintf(sy[i] * 2.f - 24.f);
        float rx = rintf(sx[i] * 2.f - 24.f);
        int syi = (int)fminf(fmaxf(ry, 0.f), (float)(HS - CROP));
        int sxi = (int)fminf(fmaxf(rx, 0.f), (float)(WSEG - CROP));
        g_start[2 * tid] = syi;
        g_start[2 * tid + 1] = sxi;
    }
}

// ================= instance conv1 as HMMA implicit GEMM =================
// grid (500, 18): crop, strip of 128 pixels. 256 threads, 8 warps (4m x 2n), warp 32x32.
// K = 288 = 9 taps (chunks) x 32 ch. B = WiT persistent in smem; A double-buffered.
#define CB_STRIDE 592                    // 288 halves * 2B + 16 pad
#define CB_BYTES (64 * CB_STRIDE)        // 37888
#define CA_BYTES (128 * ASTRIDE)         // 10240
#define CSMEM_TOTAL (CB_BYTES + 2 * CA_BYTES)  // 58368

__global__ __launch_bounds__(256) void convi_mma(
    const float* __restrict__ bi)
{
    extern __shared__ char smem[];
    uint32_t sb = smem_to_u32(smem);
    int tid = threadIdx.x;
    int wid = tid >> 5, lane = tid & 31;
    int wm = wid & 3, wn = wid >> 2;       // 4 m-warps x 2 n-warps
    int crop = blockIdx.x;
    int strip = blockIdx.y;
    int p0 = strip * 128;

    int sy = g_start[2 * crop], sx = g_start[2 * crop + 1];

    // stage B (WiT) persistent
    for (int i = tid; i < 64 * 288; i += 256) {
        int co = i / 288, k = i % 288;
        *(__half*)(smem + co * CB_STRIDE + k * 2) = g_wiT[i];
    }

    auto stageA = [&](int kt, int buf) {
        uint32_t base = sb + CB_BYTES + buf * CA_BYTES;
        int dy = kt / 3, dx = kt % 3;      // tap
#pragma unroll
        for (int q = 0; q < 2; q++) {
            int idx = tid + q * 256;
            int pix = idx >> 2, ch = idx & 3;
            int p = p0 + pix;
            int r = p / 48, c = p - r * 48;
            int rin = r + dy - 1, cin = c + dx - 1;
            bool valid = ((unsigned)rin < 48u) && ((unsigned)cin < 48u);
            size_t off = valid ? (((size_t)(sy + rin) * 512 + (sx + cin)) * 32 + ch * 8) : 0;
            unsigned sz = valid ? 16u : 0u;
            uint32_t sdst = base + pix * ASTRIDE + ch * 16;
            CP_ASYNC16(sdst, g_segh + off, sz);
        }
    };

    float acc[2][4][4];
#pragma unroll
    for (int mt = 0; mt < 2; mt++)
#pragma unroll
        for (int nt = 0; nt < 4; nt++)
#pragma unroll
            for (int i = 0; i < 4; i++) acc[mt][nt][i] = 0.f;

    int r8 = lane & 7;
    int a_rowoff = ((lane >> 3) & 1) * 8 + r8;
    int a_k16 = (lane >> 4) & 1;
    int b_rowoff = ((lane >> 4) & 1) * 8 + r8;
    int b_k16 = (lane >> 3) & 1;

    stageA(0, 0);
    CP_COMMIT();
    __syncthreads();    // B ready (also covered by later syncs)

    for (int kt = 0; kt < 9; kt++) {
        if (kt + 1 < 9) { stageA(kt + 1, (kt + 1) & 1); CP_COMMIT(); CP_WAIT1(); }
        else { CP_WAIT0(); }
        __syncthreads();

        uint32_t abase = sb + CB_BYTES + (kt & 1) * CA_BYTES;
#pragma unroll
        for (int ks = 0; ks < 2; ks++) {
            uint32_t a[2][4], b[4][2];
#pragma unroll
            for (int mt = 0; mt < 2; mt++) {
                uint32_t aaddr = abase + (wm * 32 + mt * 16 + a_rowoff) * ASTRIDE
                               + ks * 32 + a_k16 * 16;
                LDSM_X4(a[mt][0], a[mt][1], a[mt][2], a[mt][3], aaddr);
            }
#pragma unroll
            for (int pr = 0; pr < 2; pr++) {
                uint32_t baddr = sb + (wn * 32 + pr * 16 + b_rowoff) * CB_STRIDE
                               + kt * 64 + ks * 32 + b_k16 * 16;
                uint32_t t0, t1, t2, t3;
                LDSM_X4(t0, t1, t2, t3, baddr);
                b[2 * pr][0] = t0; b[2 * pr][1] = t1;
                b[2 * pr + 1][0] = t2; b[2 * pr + 1][1] = t3;
            }
#pragma unroll
            for (int mt = 0; mt < 2; mt++)
#pragma unroll
                for (int nt = 0; nt < 4; nt++)
                    MMA16816(acc[mt][nt], a[mt], b[nt][0], b[nt][1]);
        }
        __syncthreads();
    }

    int g = lane >> 2, tig = lane & 3;
#pragma unroll
    for (int mt = 0; mt < 2; mt++) {
#pragma unroll
        for (int rh = 0; rh < 2; rh++) {
            int pix = p0 + wm * 32 + mt * 16 + g + rh * 8;
#pragma unroll
            for (int nt = 0; nt < 4; nt++) {
                int n = wn * 32 + nt * 8 + 2 * tig;
                float d0 = fmaxf(acc[mt][nt][rh * 2 + 0] + bi[n], 0.f);
                float d1 = fmaxf(acc[mt][nt][rh * 2 + 1] + bi[n + 1], 0.f);
                *(__half2*)&g_h[((size_t)crop * 2304 + pix) * 64 + n] =
                    __halves2half2(__float2half(d0), __float2half(d1));
            }
        }
    }
}

// ================= instance conv2 =================
#define SMEM_O_FLOATS (10 * 48 * 65 + 576)
__global__ __launch_bounds__(384) void convo_kernel(
    const float* __restrict__ Wo, const float* __restrict__ bo, float* __restrict__ d_out)
{
    extern __shared__ float sm[];
    float* h_s = sm;
    float* wsm = sm + 10 * 48 * 65;

    int crop = blockIdx.x;
    int strip = blockIdx.y;
    int tid = threadIdx.x;

    for (int i = tid; i < 576; i += 384) wsm[i] = Wo[i];

    int r0 = strip * 8 - 1;
    for (int id = tid; id < 10 * 48 * 64; id += 384) {
        int co = id & 63;
        int rest = id >> 6;
        int cc = rest % 48;
        int rr = rest / 48;
        int rin = r0 + rr;
        float v = 0.f;
        if ((unsigned)rin < 48u)
            v = __half2float(g_h[(((size_t)crop * 48 + rin) * 48 + cc) * 64 + co]);
        h_s[(rr * 48 + cc) * 65 + co] = v;
    }
    __syncthreads();

    int r = tid / 48;
    int c = tid % 48;
    float acc = bo[0];
#pragma unroll
    for (int dy = 0; dy < 3; dy++) {
#pragma unroll
        for (int dx = 0; dx < 3; dx++) {
            int hc = c + dx - 1;
            if ((unsigned)hc < 48u) {
                const float* hb = h_s + ((r + dy) * 48 + hc) * 65;
                const float* wb = wsm + (dy * 3 + dx) * 64;
#pragma unroll 8
                for (int ci = 0; ci < 64; ci++) acc += hb[ci] * wb[ci];
            }
        }
    }
    float o = 1.f / (1.f + expf(-acc));
    int r_out = strip * 8 + r;
    size_t oi = ((size_t)crop * 48 + r_out) * 48 + c;
    d_out[OFF_INST + oi] = o;
    int syi = g_start[2 * crop], sxi = g_start[2 * crop + 1];
    d_out[OFF_COORD + oi * 2] = (float)(syi + r_out);
    d_out[OFF_COORD + oi * 2 + 1] = (float)(sxi + c);
}

// ================= launch =================
extern "C" void kernel_launch(void* const* d_in, const int* in_sizes, int n_in,
                              void* d_out, int out_size)
{
    const float* det = (const float*)d_in[0];
    const float* seg = (const float*)d_in[1];
    const float* Wc  = (const float*)d_in[2];
    const float* bc  = (const float*)d_in[3];
    const float* Wfc = (const float*)d_in[4];
    const float* bfc = (const float*)d_in[5];
    const float* Ws  = (const float*)d_in[6];
    const float* bs  = (const float*)d_in[7];
    const float* Wr  = (const float*)d_in[8];
    const float* br  = (const float*)d_in[9];
    const float* Wi  = (const float*)d_in[10];
    const float* bi  = (const float*)d_in[11];
    const float* Wo  = (const float*)d_in[12];
    const float* bo  = (const float*)d_in[13];
    float* out = (float*)d_out;

    __half *p_wt1h, *p_wt1l, *p_wt2h, *p_wt2l, *p_x1h, *p_x1l, *p_deth, *p_detl;
    cudaGetSymbolAddress((void**)&p_deth, g_deth);
    cudaGetSymbolAddress((void**)&p_detl, g_detl);
    cudaGetSymbolAddress((void**)&p_wt1h, g_wt1h);
    cudaGetSymbolAddress((void**)&p_wt1l, g_wt1l);
    cudaGetSymbolAddress((void**)&p_wt2h, g_wt2h);
    cudaGetSymbolAddress((void**)&p_wt2l, g_wt2l);
    cudaGetSymbolAddress((void**)&p_x1h, g_x1h);
    cudaGetSymbolAddress((void**)&p_x1l, g_x1l);
    float* p_x2;
    cudaGetSymbolAddress((void**)&p_x2, g_x2);

    cudaFuncSetAttribute(gemm_tc<1>, cudaFuncAttributeMaxDynamicSharedMemorySize, GSMEM_TOTAL);
    cudaFuncSetAttribute(gemm_tc<0>, cudaFuncAttributeMaxDynamicSharedMemorySize, GSMEM_TOTAL);
    cudaFuncSetAttribute(convi_mma, cudaFuncAttributeMaxDynamicSharedMemorySize, CSMEM_TOTAL);
    cudaFuncSetAttribute(convo_kernel, cudaFuncAttributeMaxDynamicSharedMemorySize,
                         SMEM_O_FLOATS * 4);

    init_kernel<<<1, 256>>>();

    // prep
    split_det_kernel<<<(NPIX * CD) / 512, 512>>>(det);
    split_seg_kernel<<<(HS * WSEG * CS) / 512, 512>>>(seg);
    prep_wiT_kernel<<<1, 256>>>(Wi);
    split_wT_kernel<<<dim3(36, 32), dim3(32, 8)>>>(Wc, p_wt1h, p_wt1l, 1152);
    split_wT_kernel<<<dim3(32, 32), dim3(32, 8)>>>(Wfc, p_wt2h, p_wt2l, 1024);

    // detection head (HMMA)
    gemm_tc<1><<<dim3(8, 512), 256, GSMEM_TOTAL>>>(
        p_deth, p_detl, p_wt1h, p_wt1l, bc, nullptr, p_x1h, p_x1l, 1152);
    gemm_tc<0><<<dim3(8, 512), 256, GSMEM_TOTAL>>>(
        p_x1h, p_x1l, p_wt2h, p_wt2l, bfc, p_x2, nullptr, nullptr, 1024);

    heads_kernel<<<8192, 256>>>(p_x2, Ws, bs, Wr, br);

    // top-2000 radix select + stable sort
    int shifts[4] = {24, 16, 8, 0};
    for (int p = 0; p < 4; p++) {
        rs_hist<<<256, 256>>>(shifts[p]);
        rs_scan<<<1, 1>>>(shifts[p]);
    }
    rs_gather<<<256, 256>>>();
    sort_kernel<<<1, 1024>>>();

    nms_kernel<<<1, 1024>>>(out);

    // instance head
    convi_mma<<<dim3(500, 18), 256, CSMEM_TOTAL>>>(bi);
    convo_kernel<<<dim3(500, 6), 384, SMEM_O_FLOATS * 4>>>(Wo, bo, out);
}

// round 16
// speedup vs baseline: 5.1038x; 1.1460x over previous
#include <cuda_runtime.h>
#include <cuda_fp16.h>
#include <math.h>
#include <cstdint>

#define HD 256
#define WD 256
#define NPIX 65536
#define CD 128
#define FC 1024
#define HS 512
#define WSEG 512
#define CS 32
#define KTOP 2000
#define MAXOUT 500
#define CROP 48
#define CI 64
#define CAND_CAP 4096

#define OFF_SCORES 0
#define OFF_DEC 500
#define OFF_INST 1500
#define OFF_COORD 1153500

// ================= small PTX helpers (non-'a' target safe) =================
__device__ __forceinline__ uint32_t smem_to_u32(const void* p) {
    uint32_t a;
    asm("{ .reg .u64 t; cvta.to.shared.u64 t, %1; cvt.u32.u64 %0, t; }" : "=r"(a) : "l"(p));
    return a;
}
#define CP_ASYNC16(sdst, gsrc, szr) \
    asm volatile("cp.async.cg.shared.global [%0], [%1], 16, %2;" \
        :: "r"(sdst), "l"(gsrc), "r"(szr))
#define CP_COMMIT() asm volatile("cp.async.commit_group;" ::: "memory")
#define CP_WAIT1()  asm volatile("cp.async.wait_group 1;" ::: "memory")
#define CP_WAIT0()  asm volatile("cp.async.wait_group 0;" ::: "memory")
#define LDSM_X4(R0, R1, R2, R3, addr) \
    asm volatile("ldmatrix.sync.aligned.m8n8.x4.shared.b16 {%0,%1,%2,%3}, [%4];" \
        : "=r"(R0), "=r"(R1), "=r"(R2), "=r"(R3) : "r"(addr))
#define MMA16816(D, A, B0, B1) \
    asm volatile("mma.sync.aligned.m16n8k16.row.col.f32.f16.f16.f32 " \
        "{%0,%1,%2,%3}, {%4,%5,%6,%7}, {%8,%9}, {%0,%1,%2,%3};" \
        : "+f"((D)[0]), "+f"((D)[1]), "+f"((D)[2]), "+f"((D)[3]) \
        : "r"((A)[0]), "r"((A)[1]), "r"((A)[2]), "r"((A)[3]), "r"(B0), "r"(B1))

// ================= scratch =================
__device__ __align__(16) __half g_deth[(size_t)NPIX * CD];
__device__ __align__(16) __half g_detl[(size_t)NPIX * CD];
__device__ __align__(16) __half g_wt1h[(size_t)FC * 1152];
__device__ __align__(16) __half g_wt1l[(size_t)FC * 1152];
__device__ __align__(16) __half g_wt2h[(size_t)FC * FC];
__device__ __align__(16) __half g_wt2l[(size_t)FC * FC];
__device__ __align__(16) __half g_x1h[(size_t)NPIX * FC];
__device__ __align__(16) __half g_x1l[(size_t)NPIX * FC];
__device__ float g_x2[(size_t)NPIX * FC];
__device__ __align__(16) __half g_segh[(size_t)HS * WSEG * CS];
__device__ __align__(16) __half g_wiT[64 * 288];
__device__ float g_logits[NPIX];
__device__ unsigned g_keys[NPIX];
__device__ float2 g_regv[NPIX];
__device__ unsigned g_counts[256];
__device__ unsigned g_prefix;
__device__ unsigned g_maskbits;
__device__ int g_want;
__device__ int g_ncand;
__device__ unsigned long long g_cand[CAND_CAP];
__device__ unsigned g_topidx[KTOP];
__device__ int g_start[MAXOUT * 2];
__device__ __align__(16) __half g_h[(size_t)MAXOUT * CROP * CROP * CI];

// ================= init =================
__global__ void init_kernel() {
    int t = threadIdx.x;
    if (t < 256) g_counts[t] = 0;
    if (t == 0) { g_prefix = 0; g_maskbits = 0; g_want = KTOP; g_ncand = 0; }
    for (int i = t; i < CAND_CAP; i += blockDim.x) g_cand[i] = 0ull;
}

// ================= split prep =================
__global__ void split_det_kernel(const float* __restrict__ det) {
    size_t i = (size_t)blockIdx.x * blockDim.x + threadIdx.x;
    float x = det[i];
    __half h = __float2half(x);
    g_deth[i] = h;
    g_detl[i] = __float2half(x - __half2float(h));
}

__global__ void split_seg_kernel(const float* __restrict__ seg) {
    size_t i = (size_t)blockIdx.x * blockDim.x + threadIdx.x;
    g_segh[i] = __float2half(seg[i]);
}

// Wi [288][64] fp32 -> WiT f16 [64][288]; grid 64 blocks (one per co)
__global__ void prep_wiT_kernel(const float* __restrict__ Wi) {
    int co = blockIdx.x;
    for (int k = threadIdx.x; k < 288; k += blockDim.x)
        g_wiT[co * 288 + k] = __float2half(Wi[k * 64 + co]);
}

// W [K][1024] fp32 -> out [1024][K] f16 hi/lo (transpose + split; lo UNSCALED — denormal f16)
__global__ void split_wT_kernel(const float* __restrict__ W, __half* __restrict__ oh,
                                __half* __restrict__ ol, int K) {
    __shared__ float s[32][33];
    int k0 = blockIdx.x * 32, n0 = blockIdx.y * 32;
    int tx = threadIdx.x, ty = threadIdx.y;   // block (32, 8)
#pragma unroll
    for (int q = 0; q < 4; q++)
        s[ty + q * 8][tx] = W[(size_t)(k0 + ty + q * 8) * 1024 + n0 + tx];
    __syncthreads();
#pragma unroll
    for (int q = 0; q < 4; q++) {
        float x = s[tx][ty + q * 8];
        __half h = __float2half(x);
        __half l = __float2half(x - __half2float(h));   // unscaled residual
        size_t o = (size_t)(n0 + ty + q * 8) * K + k0 + tx;
        oh[o] = h; ol[o] = l;
    }
}

// ================= HMMA GEMM (detection) =================
// CTA 128x128, 256 threads (8 warps, 2m x 4n), warp tile 64x32, BK=32.
// Single fp32 accumulator: acc += Ah*Bh + Al*Bh + Ah*Bl (all residuals unscaled).
#define ASTRIDE 80
#define PLANE_BYTES (128 * ASTRIDE)
#define BUF_BYTES (4 * PLANE_BYTES)
#define GSMEM_TOTAL (2 * BUF_BYTES)

template <int IM2COL>
__global__ __launch_bounds__(256, 2) void gemm_tc(
    const __half* __restrict__ Ah, const __half* __restrict__ Al,
    const __half* __restrict__ Bh, const __half* __restrict__ Bl,
    const float* __restrict__ bias,
    float* __restrict__ Cf, __half* __restrict__ Ch, __half* __restrict__ Cl, int K)
{
    extern __shared__ char smem[];
    uint32_t sb = smem_to_u32(smem);
    int tid = threadIdx.x;
    int wid = tid >> 5, lane = tid & 31;
    int wm = wid & 1, wn = wid >> 1;        // 2 m-warps x 4 n-warps
    int bx = blockIdx.x, by = blockIdx.y;
    int nb = bx * 128;
    int nch = K / 32;

    int y0 = 0, x0 = 0;
    if (IM2COL) { y0 = by >> 1; x0 = (by & 1) * 128; }

    float acc[4][4][4];
#pragma unroll
    for (int mt = 0; mt < 4; mt++)
#pragma unroll
        for (int nt = 0; nt < 4; nt++)
#pragma unroll
            for (int i = 0; i < 4; i++) acc[mt][nt][i] = 0.f;

    auto stage = [&](int kt, int buf) {
        uint32_t base = sb + buf * BUF_BYTES;
#pragma unroll
        for (int q = 0; q < 4; q++) {
            int idx = tid + q * 256;
            int plane = idx >> 9;
            int rem = idx & 511;
            int row = rem >> 2, ch = rem & 3;
            uint32_t sdst = base + plane * PLANE_BYTES + row * ASTRIDE + ch * 16;
            const __half* src;
            unsigned sz = 16;
            if (IM2COL) {
                int tap = kt >> 2;
                int c0 = (kt & 3) * 32 + ch * 8;
                int dy = tap / 3 - 1, dx = tap % 3 - 1;
                int yy = y0 + dy, xx = x0 + row + dx;
                bool valid = ((unsigned)yy < 256u) && ((unsigned)xx < 256u);
                size_t off = valid ? ((size_t)(yy * 256 + xx) * 128 + c0) : 0;
                sz = valid ? 16u : 0u;
                src = (plane ? Al : Ah) + off;
            } else {
                size_t off = (size_t)(by * 128 + row) * K + kt * 32 + ch * 8;
                src = (plane ? Al : Ah) + off;
            }
            CP_ASYNC16(sdst, src, sz);
        }
#pragma unroll
        for (int q = 0; q < 4; q++) {
            int idx = tid + q * 256;
            int plane = idx >> 9;
            int rem = idx & 511;
            int row = rem >> 2, ch = rem & 3;
            uint32_t sdst = base + (2 + plane) * PLANE_BYTES + row * ASTRIDE + ch * 16;
            size_t off = (size_t)(nb + row) * K + kt * 32 + ch * 8;
            CP_ASYNC16(sdst, (plane ? Bl : Bh) + off, 16u);
        }
    };

    int r8 = lane & 7;
    int a_rowoff = ((lane >> 3) & 1) * 8 + r8;
    int a_k16 = (lane >> 4) & 1;
    int b_rowoff = ((lane >> 4) & 1) * 8 + r8;
    int b_k16 = (lane >> 3) & 1;

    stage(0, 0);
    CP_COMMIT();

    for (int kt = 0; kt < nch; kt++) {
        if (kt + 1 < nch) { stage(kt + 1, (kt + 1) & 1); CP_COMMIT(); CP_WAIT1(); }
        else { CP_WAIT0(); }
        __syncthreads();

        uint32_t base = sb + (kt & 1) * BUF_BYTES;
#pragma unroll
        for (int ks = 0; ks < 2; ks++) {
            uint32_t ah[4][4], al[4][4], bh[4][2], bl[4][2];
#pragma unroll
            for (int mt = 0; mt < 4; mt++) {
                uint32_t aaddr = base + (wm * 64 + mt * 16 + a_rowoff) * ASTRIDE
                               + ks * 32 + a_k16 * 16;
                LDSM_X4(ah[mt][0], ah[mt][1], ah[mt][2], ah[mt][3], aaddr);
                LDSM_X4(al[mt][0], al[mt][1], al[mt][2], al[mt][3], aaddr + PLANE_BYTES);
            }
#pragma unroll
            for (int pr = 0; pr < 2; pr++) {
                uint32_t baddr = base + 2 * PLANE_BYTES
                               + (wn * 32 + pr * 16 + b_rowoff) * ASTRIDE
                               + ks * 32 + b_k16 * 16;
                uint32_t t0, t1, t2, t3;
                LDSM_X4(t0, t1, t2, t3, baddr);
                bh[2 * pr][0] = t0; bh[2 * pr][1] = t1;
                bh[2 * pr + 1][0] = t2; bh[2 * pr + 1][1] = t3;
                LDSM_X4(t0, t1, t2, t3, baddr + PLANE_BYTES);
                bl[2 * pr][0] = t0; bl[2 * pr][1] = t1;
                bl[2 * pr + 1][0] = t2; bl[2 * pr + 1][1] = t3;
            }
#pragma unroll
            for (int mt = 0; mt < 4; mt++)
#pragma unroll
                for (int nt = 0; nt < 4; nt++) {
                    MMA16816(acc[mt][nt], ah[mt], bh[nt][0], bh[nt][1]);
                    MMA16816(acc[mt][nt], al[mt], bh[nt][0], bh[nt][1]);
                    MMA16816(acc[mt][nt], ah[mt], bl[nt][0], bl[nt][1]);
                }
        }
        __syncthreads();
    }

    int g = lane >> 2, tig = lane & 3;
#pragma unroll
    for (int mt = 0; mt < 4; mt++) {
#pragma unroll
        for (int rh = 0; rh < 2; rh++) {
            int mloc = wm * 64 + mt * 16 + g + rh * 8;
            size_t mg = (size_t)(by * 128 + mloc);
#pragma unroll
            for (int nt = 0; nt < 4; nt++) {
                int ncol = nb + wn * 32 + nt * 8 + 2 * tig;
                float d0 = fmaxf(acc[mt][nt][rh * 2 + 0] + bias[ncol], 0.f);
                float d1 = fmaxf(acc[mt][nt][rh * 2 + 1] + bias[ncol + 1], 0.f);
                if (IM2COL) {
                    __half h0 = __float2half(d0), h1 = __float2half(d1);
                    __half l0 = __float2half(d0 - __half2float(h0));
                    __half l1 = __float2half(d1 - __half2float(h1));
                    *(__half2*)&Ch[mg * 1024 + ncol] = __halves2half2(h0, h1);
                    *(__half2*)&Cl[mg * 1024 + ncol] = __halves2half2(l0, l1);
                } else {
                    *(float2*)&Cf[mg * 1024 + ncol] = make_float2(d0, d1);
                }
            }
        }
    }
}

// ================= heads =================
__global__ void heads_kernel(const float* __restrict__ x2,
                             const float* __restrict__ Ws, const float* __restrict__ bs,
                             const float* __restrict__ Wr, const float* __restrict__ br)
{
    int gid = blockIdx.x * blockDim.x + threadIdx.x;
    int m = gid >> 5;
    int lane = threadIdx.x & 31;
    if (m >= NPIX) return;
    const float* xr = x2 + (size_t)m * 1024;
    float s = 0.f, r0 = 0.f, r1 = 0.f;
    for (int c = lane; c < 1024; c += 32) {
        float x = xr[c];
        s += x * Ws[c];
        r0 += x * Wr[2 * c];
        r1 += x * Wr[2 * c + 1];
    }
#pragma unroll
    for (int o = 16; o; o >>= 1) {
        s  += __shfl_down_sync(0xFFFFFFFFu, s, o);
        r0 += __shfl_down_sync(0xFFFFFFFFu, r0, o);
        r1 += __shfl_down_sync(0xFFFFFFFFu, r1, o);
    }
    if (lane == 0) {
        float logit = s + bs[0];
        g_logits[m] = logit;
        unsigned b = __float_as_uint(logit);
        g_keys[m] = (b & 0x80000000u) ? ~b : (b | 0x80000000u);
        g_regv[m] = make_float2(r0 + br[0], r1 + br[1]);
    }
}

// ================= radix select =================
__global__ void rs_hist(int shift) {
    __shared__ unsigned hc[256];
    int t = threadIdx.x;
    hc[t] = 0;
    __syncthreads();
    int m = blockIdx.x * 256 + t;
    unsigned key = g_keys[m];
    if ((key & g_maskbits) == g_prefix)
        atomicAdd(&hc[(key >> shift) & 0xFFu], 1u);
    __syncthreads();
    if (hc[t]) atomicAdd(&g_counts[t], hc[t]);
}

__global__ void rs_scan(int shift) {
    int want = g_want;
    unsigned cum = 0;
    int sel = 0;
    for (int b = 255; b >= 0; b--) {
        unsigned c = g_counts[b];
        if (cum + c >= (unsigned)want) { sel = b; g_want = want - (int)cum; break; }
        cum += c;
    }
    g_prefix |= ((unsigned)sel) << shift;
    g_maskbits |= 0xFFu << shift;
    for (int b = 0; b < 256; b++) g_counts[b] = 0;
}

__global__ void rs_gather() {
    int m = blockIdx.x * 256 + threadIdx.x;
    unsigned key = g_keys[m];
    if (key >= g_prefix) {
        int p = atomicAdd(&g_ncand, 1);
        if (p < CAND_CAP)
            g_cand[p] = ((unsigned long long)key << 32) | (unsigned)(~m);
    }
}

// ================= bitonic sort =================
__global__ void sort_kernel() {
    __shared__ unsigned long long s[CAND_CAP];
    int tid = threadIdx.x;
    for (int i = tid; i < CAND_CAP; i += 1024) s[i] = g_cand[i];
    __syncthreads();
    for (int k = 2; k <= CAND_CAP; k <<= 1) {
        for (int j = k >> 1; j > 0; j >>= 1) {
#pragma unroll
            for (int q = 0; q < 4; q++) {
                int t = tid + q * 1024;
                int ixj = t ^ j;
                if (ixj > t) {
                    unsigned long long a = s[t], b = s[ixj];
                    bool seg = (t & k) == 0;
                    if (seg ? (a < b) : (a > b)) { s[t] = b; s[ixj] = a; }
                }
            }
            __syncthreads();
        }
    }
    for (int i = tid; i < KTOP; i += 1024)
        g_topidx[i] = ~((unsigned)(s[i] & 0xFFFFFFFFull));
}

// ================= NMS + top-500 =================
__global__ void nms_kernel(float* __restrict__ d_out) {
    __shared__ float sy[KTOP], sx[KTOP], slog[KTOP];
    __shared__ unsigned char supp[KTOP];
    __shared__ int sel[MAXOUT];
    __shared__ float selsc[MAXOUT];
    int tid = threadIdx.x;
    for (int i = tid; i < KTOP; i += 1024) {
        unsigned idx = g_topidx[i];
        int y = idx >> 8;
        int x = idx & 255;
        float2 r = g_regv[idx];
        sy[i] = (float)y + 0.5f + r.x;
        sx[i] = (float)x + 0.5f + r.y;
        slog[i] = g_logits[idx];
        supp[i] = 0;
    }
    __syncthreads();
    for (int i = 0; i < KTOP; i++) {
        if (!supp[i]) {
            float by = sy[i], bx = sx[i];
#pragma unroll
            for (int q = 0; q < 2; q++) {
                int j = tid + q * 1024;
                if (j > i && j < KTOP && !supp[j]) {
                    float dy = sy[j] - by;
                    float dx = sx[j] - bx;
                    if (dy * dy + dx * dx < 1.0f) supp[j] = 1;
                }
            }
        }
        __syncthreads();
    }
    if (tid == 0) {
        int c = 0;
        for (int i = 0; i < KTOP && c < MAXOUT; i++)
            if (!supp[i]) { sel[c] = i; selsc[c] = 1.f / (1.f + expf(-slog[i])); c++; }
        for (int i = 0; i < KTOP && c < MAXOUT; i++)
            if (supp[i]) { sel[c] = i; selsc[c] = -1.f; c++; }
    }
    __syncthreads();
    if (tid < MAXOUT) {
        int i = sel[tid];
        d_out[OFF_SCORES + tid] = selsc[tid];
        d_out[OFF_DEC + 2 * tid] = sy[i] * 4.f;
        d_out[OFF_DEC + 2 * tid + 1] = sx[i] * 4.f;
        float ry = rintf(sy[i] * 2.f - 24.f);
        float rx = rintf(sx[i] * 2.f - 24.f);
        int syi = (int)fminf(fmaxf(ry, 0.f), (float)(HS - CROP));
        int sxi = (int)fminf(fmaxf(rx, 0.f), (float)(WSEG - CROP));
        g_start[2 * tid] = syi;
        g_start[2 * tid + 1] = sxi;
    }
}

// ================= instance conv1 as HMMA implicit GEMM =================
// grid (500, 9): crop, strip of 256 pixels. 256 threads, 8 warps (4m x 2n), warp 64x32.
// K = 288 = 9 taps (chunks) x 32 ch. B = WiT persistent in smem; A double-buffered.
#define CB_STRIDE 592                    // 288 halves * 2B + 16 pad
#define CB_BYTES (64 * CB_STRIDE)        // 37888
#define CA_BYTES (256 * ASTRIDE)         // 20480
#define CSMEM_TOTAL (CB_BYTES + 2 * CA_BYTES)  // 78848

__global__ __launch_bounds__(256, 2) void convi_mma(
    const float* __restrict__ bi)
{
    extern __shared__ char smem[];
    uint32_t sb = smem_to_u32(smem);
    int tid = threadIdx.x;
    int wid = tid >> 5, lane = tid & 31;
    int wm = wid & 3, wn = wid >> 2;       // 4 m-warps x 2 n-warps
    int crop = blockIdx.x;
    int strip = blockIdx.y;
    int p0 = strip * 256;

    int sy = g_start[2 * crop], sx = g_start[2 * crop + 1];

    // stage B (WiT) persistent
    for (int i = tid; i < 64 * 288; i += 256) {
        int co = i / 288, k = i % 288;
        *(__half*)(smem + co * CB_STRIDE + k * 2) = g_wiT[i];
    }

    auto stageA = [&](int kt, int buf) {
        uint32_t base = sb + CB_BYTES + buf * CA_BYTES;
        int dy = kt / 3, dx = kt % 3;      // tap
#pragma unroll
        for (int q = 0; q < 4; q++) {
            int idx = tid + q * 256;
            int pix = idx >> 2, ch = idx & 3;
            int p = p0 + pix;
            int r = p / 48, c = p - r * 48;
            int rin = r + dy - 1, cin = c + dx - 1;
            bool valid = ((unsigned)rin < 48u) && ((unsigned)cin < 48u);
            size_t off = valid ? (((size_t)(sy + rin) * 512 + (sx + cin)) * 32 + ch * 8) : 0;
            unsigned sz = valid ? 16u : 0u;
            uint32_t sdst = base + pix * ASTRIDE + ch * 16;
            CP_ASYNC16(sdst, g_segh + off, sz);
        }
    };

    float acc[4][2][4];
#pragma unroll
    for (int mt = 0; mt < 4; mt++)
#pragma unroll
        for (int nt = 0; nt < 2; nt++)
#pragma unroll
            for (int i = 0; i < 4; i++) acc[mt][nt][i] = 0.f;
    float acc2[4][2][4];
#pragma unroll
    for (int mt = 0; mt < 4; mt++)
#pragma unroll
        for (int nt = 0; nt < 2; nt++)
#pragma unroll
            for (int i = 0; i < 4; i++) acc2[mt][nt][i] = 0.f;

    int r8 = lane & 7;
    int a_rowoff = ((lane >> 3) & 1) * 8 + r8;
    int a_k16 = (lane >> 4) & 1;
    int b_rowoff = ((lane >> 4) & 1) * 8 + r8;
    int b_k16 = (lane >> 3) & 1;

    stageA(0, 0);
    CP_COMMIT();
    __syncthreads();    // B ready

    for (int kt = 0; kt < 9; kt++) {
        if (kt + 1 < 9) { stageA(kt + 1, (kt + 1) & 1); CP_COMMIT(); CP_WAIT1(); }
        else { CP_WAIT0(); }
        __syncthreads();

        uint32_t abase = sb + CB_BYTES + (kt & 1) * CA_BYTES;
#pragma unroll
        for (int ks = 0; ks < 2; ks++) {
            uint32_t a[4][4], b[4][2];
#pragma unroll
            for (int mt = 0; mt < 4; mt++) {
                uint32_t aaddr = abase + (wm * 64 + mt * 16 + a_rowoff) * ASTRIDE
                               + ks * 32 + a_k16 * 16;
                LDSM_X4(a[mt][0], a[mt][1], a[mt][2], a[mt][3], aaddr);
            }
#pragma unroll
            for (int pr = 0; pr < 2; pr++) {
                uint32_t baddr = sb + (wn * 32 + pr * 16 + b_rowoff) * CB_STRIDE
                               + kt * 64 + ks * 32 + b_k16 * 16;
                uint32_t t0, t1, t2, t3;
                LDSM_X4(t0, t1, t2, t3, baddr);
                b[2 * pr][0] = t0; b[2 * pr][1] = t1;
                b[2 * pr + 1][0] = t2; b[2 * pr + 1][1] = t3;
            }
#pragma unroll
            for (int mt = 0; mt < 4; mt++) {
#pragma unroll
                for (int nt = 0; nt < 2; nt++) {
                    MMA16816(acc[mt][nt], a[mt], b[nt][0], b[nt][1]);
                    MMA16816(acc2[mt][nt], a[mt], b[2 + nt][0], b[2 + nt][1]);
                }
            }
        }
        __syncthreads();
    }

    int g = lane >> 2, tig = lane & 3;
#pragma unroll
    for (int mt = 0; mt < 4; mt++) {
#pragma unroll
        for (int rh = 0; rh < 2; rh++) {
            int pix = p0 + wm * 64 + mt * 16 + g + rh * 8;
#pragma unroll
            for (int nt = 0; nt < 4; nt++) {
                int n = wn * 32 + nt * 8 + 2 * tig;
                float v0 = (nt < 2) ? acc[mt][nt][rh * 2 + 0] : acc2[mt][nt - 2][rh * 2 + 0];
                float v1 = (nt < 2) ? acc[mt][nt][rh * 2 + 1] : acc2[mt][nt - 2][rh * 2 + 1];
                float d0 = fmaxf(v0 + bi[n], 0.f);
                float d1 = fmaxf(v1 + bi[n + 1], 0.f);
                *(__half2*)&g_h[((size_t)crop * 2304 + pix) * 64 + n] =
                    __halves2half2(__float2half(d0), __float2half(d1));
            }
        }
    }
}

// ================= instance conv2 =================
#define SMEM_O_FLOATS (10 * 48 * 65 + 576)
__global__ __launch_bounds__(384) void convo_kernel(
    const float* __restrict__ Wo, const float* __restrict__ bo, float* __restrict__ d_out)
{
    extern __shared__ float sm[];
    float* h_s = sm;
    float* wsm = sm + 10 * 48 * 65;

    int crop = blockIdx.x;
    int strip = blockIdx.y;
    int tid = threadIdx.x;

    for (int i = tid; i < 576; i += 384) wsm[i] = Wo[i];

    int r0 = strip * 8 - 1;
    for (int id = tid; id < 10 * 48 * 64; id += 384) {
        int co = id & 63;
        int rest = id >> 6;
        int cc = rest % 48;
        int rr = rest / 48;
        int rin = r0 + rr;
        float v = 0.f;
        if ((unsigned)rin < 48u)
            v = __half2float(g_h[(((size_t)crop * 48 + rin) * 48 + cc) * 64 + co]);
        h_s[(rr * 48 + cc) * 65 + co] = v;
    }
    __syncthreads();

    int r = tid / 48;
    int c = tid % 48;
    float acc = bo[0];
#pragma unroll
    for (int dy = 0; dy < 3; dy++) {
#pragma unroll
        for (int dx = 0; dx < 3; dx++) {
            int hc = c + dx - 1;
            if ((unsigned)hc < 48u) {
                const float* hb = h_s + ((r + dy) * 48 + hc) * 65;
                const float* wb = wsm + (dy * 3 + dx) * 64;
#pragma unroll 8
                for (int ci = 0; ci < 64; ci++) acc += hb[ci] * wb[ci];
            }
        }
    }
    float o = 1.f / (1.f + expf(-acc));
    int r_out = strip * 8 + r;
    size_t oi = ((size_t)crop * 48 + r_out) * 48 + c;
    d_out[OFF_INST + oi] = o;
    int syi = g_start[2 * crop], sxi = g_start[2 * crop + 1];
    d_out[OFF_COORD + oi * 2] = (float)(syi + r_out);
    d_out[OFF_COORD + oi * 2 + 1] = (float)(sxi + c);
}

// ================= launch =================
extern "C" void kernel_launch(void* const* d_in, const int* in_sizes, int n_in,
                              void* d_out, int out_size)
{
    const float* det = (const float*)d_in[0];
    const float* seg = (const float*)d_in[1];
    const float* Wc  = (const float*)d_in[2];
    const float* bc  = (const float*)d_in[3];
    const float* Wfc = (const float*)d_in[4];
    const float* bfc = (const float*)d_in[5];
    const float* Ws  = (const float*)d_in[6];
    const float* bs  = (const float*)d_in[7];
    const float* Wr  = (const float*)d_in[8];
    const float* br  = (const float*)d_in[9];
    const float* Wi  = (const float*)d_in[10];
    const float* bi  = (const float*)d_in[11];
    const float* Wo  = (const float*)d_in[12];
    const float* bo  = (const float*)d_in[13];
    float* out = (float*)d_out;

    __half *p_wt1h, *p_wt1l, *p_wt2h, *p_wt2l, *p_x1h, *p_x1l, *p_deth, *p_detl;
    cudaGetSymbolAddress((void**)&p_deth, g_deth);
    cudaGetSymbolAddress((void**)&p_detl, g_detl);
    cudaGetSymbolAddress((void**)&p_wt1h, g_wt1h);
    cudaGetSymbolAddress((void**)&p_wt1l, g_wt1l);
    cudaGetSymbolAddress((void**)&p_wt2h, g_wt2h);
    cudaGetSymbolAddress((void**)&p_wt2l, g_wt2l);
    cudaGetSymbolAddress((void**)&p_x1h, g_x1h);
    cudaGetSymbolAddress((void**)&p_x1l, g_x1l);
    float* p_x2;
    cudaGetSymbolAddress((void**)&p_x2, g_x2);

    cudaFuncSetAttribute(gemm_tc<1>, cudaFuncAttributeMaxDynamicSharedMemorySize, GSMEM_TOTAL);
    cudaFuncSetAttribute(gemm_tc<0>, cudaFuncAttributeMaxDynamicSharedMemorySize, GSMEM_TOTAL);
    cudaFuncSetAttribute(convi_mma, cudaFuncAttributeMaxDynamicSharedMemorySize, CSMEM_TOTAL);
    cudaFuncSetAttribute(convo_kernel, cudaFuncAttributeMaxDynamicSharedMemorySize,
                         SMEM_O_FLOATS * 4);

    init_kernel<<<1, 256>>>();

    // prep
    split_det_kernel<<<(NPIX * CD) / 512, 512>>>(det);
    split_seg_kernel<<<(HS * WSEG * CS) / 512, 512>>>(seg);
    prep_wiT_kernel<<<64, 128>>>(Wi);
    split_wT_kernel<<<dim3(36, 32), dim3(32, 8)>>>(Wc, p_wt1h, p_wt1l, 1152);
    split_wT_kernel<<<dim3(32, 32), dim3(32, 8)>>>(Wfc, p_wt2h, p_wt2l, 1024);

    // detection head (HMMA)
    gemm_tc<1><<<dim3(8, 512), 256, GSMEM_TOTAL>>>(
        p_deth, p_detl, p_wt1h, p_wt1l, bc, nullptr, p_x1h, p_x1l, 1152);
    gemm_tc<0><<<dim3(8, 512), 256, GSMEM_TOTAL>>>(
        p_x1h, p_x1l, p_wt2h, p_wt2l, bfc, p_x2, nullptr, nullptr, 1024);

    heads_kernel<<<8192, 256>>>(p_x2, Ws, bs, Wr, br);

    // top-2000 radix select + stable sort
    int shifts[4] = {24, 16, 8, 0};
    for (int p = 0; p < 4; p++) {
        rs_hist<<<256, 256>>>(shifts[p]);
        rs_scan<<<1, 1>>>(shifts[p]);
    }
    rs_gather<<<256, 256>>>();
    sort_kernel<<<1, 1024>>>();

    nms_kernel<<<1, 1024>>>(out);

    // instance head
    convi_mma<<<dim3(500, 9), 256, CSMEM_TOTAL>>>(bi);
    convo_kernel<<<dim3(500, 6), 384, SMEM_O_FLOATS * 4>>>(Wo, bo, out);
}

// round 17
// speedup vs baseline: 5.6634x; 1.1096x over previous
#include <cuda_runtime.h>
#include <cuda_fp16.h>
#include <math.h>
#include <cstdint>

#define HD 256
#define WD 256
#define NPIX 65536
#define CD 128
#define FC 1024
#define HS 512
#define WSEG 512
#define CS 32
#define KTOP 2000
#define MAXOUT 500
#define CROP 48
#define CI 64
#define CAND_CAP 4096

#define OFF_SCORES 0
#define OFF_DEC 500
#define OFF_INST 1500
#define OFF_COORD 1153500

// ================= small PTX helpers (non-'a' target safe) =================
__device__ __forceinline__ uint32_t smem_to_u32(const void* p) {
    uint32_t a;
    asm("{ .reg .u64 t; cvta.to.shared.u64 t, %1; cvt.u32.u64 %0, t; }" : "=r"(a) : "l"(p));
    return a;
}
#define CP_ASYNC16(sdst, gsrc, szr) \
    asm volatile("cp.async.cg.shared.global [%0], [%1], 16, %2;" \
        :: "r"(sdst), "l"(gsrc), "r"(szr))
#define CP_COMMIT() asm volatile("cp.async.commit_group;" ::: "memory")
#define CP_WAIT1()  asm volatile("cp.async.wait_group 1;" ::: "memory")
#define CP_WAIT0()  asm volatile("cp.async.wait_group 0;" ::: "memory")
#define LDSM_X4(R0, R1, R2, R3, addr) \
    asm volatile("ldmatrix.sync.aligned.m8n8.x4.shared.b16 {%0,%1,%2,%3}, [%4];" \
        : "=r"(R0), "=r"(R1), "=r"(R2), "=r"(R3) : "r"(addr))
#define MMA16816(D, A, B0, B1) \
    asm volatile("mma.sync.aligned.m16n8k16.row.col.f32.f16.f16.f32 " \
        "{%0,%1,%2,%3}, {%4,%5,%6,%7}, {%8,%9}, {%0,%1,%2,%3};" \
        : "+f"((D)[0]), "+f"((D)[1]), "+f"((D)[2]), "+f"((D)[3]) \
        : "r"((A)[0]), "r"((A)[1]), "r"((A)[2]), "r"((A)[3]), "r"(B0), "r"(B1))

// ================= scratch =================
__device__ __align__(16) __half g_deth[(size_t)NPIX * CD];
__device__ __align__(16) __half g_detl[(size_t)NPIX * CD];
__device__ __align__(16) __half g_wt1h[(size_t)FC * 1152];
__device__ __align__(16) __half g_wt1l[(size_t)FC * 1152];
__device__ __align__(16) __half g_wt2h[(size_t)FC * FC];
__device__ __align__(16) __half g_wt2l[(size_t)FC * FC];
__device__ __align__(16) __half g_x1h[(size_t)NPIX * FC];
__device__ __align__(16) __half g_x1l[(size_t)NPIX * FC];
__device__ __align__(16) float g_hp[(size_t)NPIX * 8 * 3];   // per-CTA head partials
__device__ __align__(16) __half g_segh[(size_t)HS * WSEG * CS];
__device__ __align__(16) __half g_wiT[64 * 288];
__device__ float g_logits[NPIX];
__device__ unsigned g_keys[NPIX];
__device__ float2 g_regv[NPIX];
__device__ unsigned g_counts[256];
__device__ unsigned g_prefix;
__device__ unsigned g_maskbits;
__device__ int g_want;
__device__ int g_ncand;
__device__ unsigned long long g_cand[CAND_CAP];
__device__ unsigned g_topidx[KTOP];
__device__ int g_start[MAXOUT * 2];
__device__ __align__(16) __half g_h[(size_t)MAXOUT * CROP * CROP * CI];

// ================= init =================
__global__ void init_kernel() {
    int t = threadIdx.x;
    if (t < 256) g_counts[t] = 0;
    if (t == 0) { g_prefix = 0; g_maskbits = 0; g_want = KTOP; g_ncand = 0; }
    for (int i = t; i < CAND_CAP; i += blockDim.x) g_cand[i] = 0ull;
}

// ================= split prep =================
__global__ void split_det_kernel(const float* __restrict__ det) {
    size_t i = (size_t)blockIdx.x * blockDim.x + threadIdx.x;
    float x = det[i];
    __half h = __float2half(x);
    g_deth[i] = h;
    g_detl[i] = __float2half(x - __half2float(h));
}

__global__ void split_seg_kernel(const float* __restrict__ seg) {
    size_t i = (size_t)blockIdx.x * blockDim.x + threadIdx.x;
    g_segh[i] = __float2half(seg[i]);
}

__global__ void prep_wiT_kernel(const float* __restrict__ Wi) {
    int co = blockIdx.x;
    for (int k = threadIdx.x; k < 288; k += blockDim.x)
        g_wiT[co * 288 + k] = __float2half(Wi[k * 64 + co]);
}

// W [K][1024] fp32 -> out [1024][K] f16 hi/lo (transpose + split; lo UNSCALED)
__global__ void split_wT_kernel(const float* __restrict__ W, __half* __restrict__ oh,
                                __half* __restrict__ ol, int K) {
    __shared__ float s[32][33];
    int k0 = blockIdx.x * 32, n0 = blockIdx.y * 32;
    int tx = threadIdx.x, ty = threadIdx.y;   // block (32, 8)
#pragma unroll
    for (int q = 0; q < 4; q++)
        s[ty + q * 8][tx] = W[(size_t)(k0 + ty + q * 8) * 1024 + n0 + tx];
    __syncthreads();
#pragma unroll
    for (int q = 0; q < 4; q++) {
        float x = s[tx][ty + q * 8];
        __half h = __float2half(x);
        __half l = __float2half(x - __half2float(h));
        size_t o = (size_t)(n0 + ty + q * 8) * K + k0 + tx;
        oh[o] = h; ol[o] = l;
    }
}

// ================= HMMA GEMM (detection) =================
// CTA 128x128, 256 threads (8 warps, 2m x 4n), warp tile 64x32, BK=32.
// acc += Ah*Bh + Al*Bh + Ah*Bl (residuals unscaled).
// HEADS=1: instead of storing C, compute per-CTA head partials (deterministic).
#define ASTRIDE 80
#define PLANE_BYTES (128 * ASTRIDE)
#define BUF_BYTES (4 * PLANE_BYTES)
#define GSMEM_TOTAL (2 * BUF_BYTES)

template <int IM2COL, int HEADS>
__global__ __launch_bounds__(256, 2) void gemm_tc(
    const __half* __restrict__ Ah, const __half* __restrict__ Al,
    const __half* __restrict__ Bh, const __half* __restrict__ Bl,
    const float* __restrict__ bias,
    const float* __restrict__ Wsc, const float* __restrict__ Wrg,
    __half* __restrict__ Ch, __half* __restrict__ Cl, int K)
{
    extern __shared__ char smem[];
    uint32_t sb = smem_to_u32(smem);
    int tid = threadIdx.x;
    int wid = tid >> 5, lane = tid & 31;
    int wm = wid & 1, wn = wid >> 1;        // 2 m-warps x 4 n-warps
    int bx = blockIdx.x, by = blockIdx.y;
    int nb = bx * 128;
    int nch = K / 32;

    int y0 = 0, x0 = 0;
    if (IM2COL) { y0 = by >> 1; x0 = (by & 1) * 128; }

    float acc[4][4][4];
#pragma unroll
    for (int mt = 0; mt < 4; mt++)
#pragma unroll
        for (int nt = 0; nt < 4; nt++)
#pragma unroll
            for (int i = 0; i < 4; i++) acc[mt][nt][i] = 0.f;

    auto stage = [&](int kt, int buf) {
        uint32_t base = sb + buf * BUF_BYTES;
#pragma unroll
        for (int q = 0; q < 4; q++) {
            int idx = tid + q * 256;
            int plane = idx >> 9;
            int rem = idx & 511;
            int row = rem >> 2, ch = rem & 3;
            uint32_t sdst = base + plane * PLANE_BYTES + row * ASTRIDE + ch * 16;
            const __half* src;
            unsigned sz = 16;
            if (IM2COL) {
                int tap = kt >> 2;
                int c0 = (kt & 3) * 32 + ch * 8;
                int dy = tap / 3 - 1, dx = tap % 3 - 1;
                int yy = y0 + dy, xx = x0 + row + dx;
                bool valid = ((unsigned)yy < 256u) && ((unsigned)xx < 256u);
                size_t off = valid ? ((size_t)(yy * 256 + xx) * 128 + c0) : 0;
                sz = valid ? 16u : 0u;
                src = (plane ? Al : Ah) + off;
            } else {
                size_t off = (size_t)(by * 128 + row) * K + kt * 32 + ch * 8;
                src = (plane ? Al : Ah) + off;
            }
            CP_ASYNC16(sdst, src, sz);
        }
#pragma unroll
        for (int q = 0; q < 4; q++) {
            int idx = tid + q * 256;
            int plane = idx >> 9;
            int rem = idx & 511;
            int row = rem >> 2, ch = rem & 3;
            uint32_t sdst = base + (2 + plane) * PLANE_BYTES + row * ASTRIDE + ch * 16;
            size_t off = (size_t)(nb + row) * K + kt * 32 + ch * 8;
            CP_ASYNC16(sdst, (plane ? Bl : Bh) + off, 16u);
        }
    };

    int r8 = lane & 7;
    int a_rowoff = ((lane >> 3) & 1) * 8 + r8;
    int a_k16 = (lane >> 4) & 1;
    int b_rowoff = ((lane >> 4) & 1) * 8 + r8;
    int b_k16 = (lane >> 3) & 1;

    stage(0, 0);
    CP_COMMIT();

    for (int kt = 0; kt < nch; kt++) {
        if (kt + 1 < nch) { stage(kt + 1, (kt + 1) & 1); CP_COMMIT(); CP_WAIT1(); }
        else { CP_WAIT0(); }
        __syncthreads();

        uint32_t base = sb + (kt & 1) * BUF_BYTES;
#pragma unroll
        for (int ks = 0; ks < 2; ks++) {
            uint32_t ah[4][4], al[4][4], bh[4][2], bl[4][2];
#pragma unroll
            for (int mt = 0; mt < 4; mt++) {
                uint32_t aaddr = base + (wm * 64 + mt * 16 + a_rowoff) * ASTRIDE
                               + ks * 32 + a_k16 * 16;
                LDSM_X4(ah[mt][0], ah[mt][1], ah[mt][2], ah[mt][3], aaddr);
                LDSM_X4(al[mt][0], al[mt][1], al[mt][2], al[mt][3], aaddr + PLANE_BYTES);
            }
#pragma unroll
            for (int pr = 0; pr < 2; pr++) {
                uint32_t baddr = base + 2 * PLANE_BYTES
                               + (wn * 32 + pr * 16 + b_rowoff) * ASTRIDE
                               + ks * 32 + b_k16 * 16;
                uint32_t t0, t1, t2, t3;
                LDSM_X4(t0, t1, t2, t3, baddr);
                bh[2 * pr][0] = t0; bh[2 * pr][1] = t1;
                bh[2 * pr + 1][0] = t2; bh[2 * pr + 1][1] = t3;
                LDSM_X4(t0, t1, t2, t3, baddr + PLANE_BYTES);
                bl[2 * pr][0] = t0; bl[2 * pr][1] = t1;
                bl[2 * pr + 1][0] = t2; bl[2 * pr + 1][1] = t3;
            }
#pragma unroll
            for (int mt = 0; mt < 4; mt++)
#pragma unroll
                for (int nt = 0; nt < 4; nt++) {
                    MMA16816(acc[mt][nt], ah[mt], bh[nt][0], bh[nt][1]);
                    MMA16816(acc[mt][nt], al[mt], bh[nt][0], bh[nt][1]);
                    MMA16816(acc[mt][nt], ah[mt], bl[nt][0], bl[nt][1]);
                }
        }
        __syncthreads();
    }

    int g = lane >> 2, tig = lane & 3;

    if (HEADS) {
        // smem reuse: swB[128] bias, swS[128] Ws, swR[128][2] Wr, part[4][128][3]
        float* swB = (float*)smem;
        float* swS = swB + 128;
        float* swR = swS + 128;                 // [128*2]
        float* part = swR + 256;                // [4*128*3]
        if (tid < 128) {
            swB[tid] = bias[nb + tid];
            swS[tid] = Wsc[nb + tid];
            float2 wr = *(const float2*)&Wrg[2 * (nb + tid)];
            swR[tid * 2] = wr.x; swR[tid * 2 + 1] = wr.y;
        }
        __syncthreads();
#pragma unroll
        for (int mt = 0; mt < 4; mt++) {
#pragma unroll
            for (int rh = 0; rh < 2; rh++) {
                int rloc = wm * 64 + mt * 16 + g + rh * 8;
                float s = 0.f, r0 = 0.f, r1 = 0.f;
#pragma unroll
                for (int nt = 0; nt < 4; nt++) {
                    int nl = wn * 32 + nt * 8 + 2 * tig;
                    float d0 = fmaxf(acc[mt][nt][rh * 2 + 0] + swB[nl], 0.f);
                    float d1 = fmaxf(acc[mt][nt][rh * 2 + 1] + swB[nl + 1], 0.f);
                    s  += d0 * swS[nl] + d1 * swS[nl + 1];
                    r0 += d0 * swR[nl * 2] + d1 * swR[(nl + 1) * 2];
                    r1 += d0 * swR[nl * 2 + 1] + d1 * swR[(nl + 1) * 2 + 1];
                }
                s  += __shfl_xor_sync(0xFFFFFFFFu, s, 1);
                s  += __shfl_xor_sync(0xFFFFFFFFu, s, 2);
                r0 += __shfl_xor_sync(0xFFFFFFFFu, r0, 1);
                r0 += __shfl_xor_sync(0xFFFFFFFFu, r0, 2);
                r1 += __shfl_xor_sync(0xFFFFFFFFu, r1, 1);
                r1 += __shfl_xor_sync(0xFFFFFFFFu, r1, 2);
                if (tig == 0) {
                    float* p = part + (wn * 128 + rloc) * 3;
                    p[0] = s; p[1] = r0; p[2] = r1;
                }
            }
        }
        __syncthreads();
        if (tid < 128) {
            float s = 0.f, r0 = 0.f, r1 = 0.f;
#pragma unroll
            for (int w = 0; w < 4; w++) {
                float* p = part + (w * 128 + tid) * 3;
                s += p[0]; r0 += p[1]; r1 += p[2];
            }
            size_t m = (size_t)by * 128 + tid;
            float* dst = &g_hp[(m * 8 + bx) * 3];
            dst[0] = s; dst[1] = r0; dst[2] = r1;
        }
        return;
    }

    // C store path (GEMM1 -> x1 split)
#pragma unroll
    for (int mt = 0; mt < 4; mt++) {
#pragma unroll
        for (int rh = 0; rh < 2; rh++) {
            int mloc = wm * 64 + mt * 16 + g + rh * 8;
            size_t mg = (size_t)(by * 128 + mloc);
#pragma unroll
            for (int nt = 0; nt < 4; nt++) {
                int ncol = nb + wn * 32 + nt * 8 + 2 * tig;
                float d0 = fmaxf(acc[mt][nt][rh * 2 + 0] + bias[ncol], 0.f);
                float d1 = fmaxf(acc[mt][nt][rh * 2 + 1] + bias[ncol + 1], 0.f);
                __half h0 = __float2half(d0), h1 = __float2half(d1);
                __half l0 = __float2half(d0 - __half2float(h0));
                __half l1 = __float2half(d1 - __half2float(h1));
                *(__half2*)&Ch[mg * 1024 + ncol] = __halves2half2(h0, h1);
                *(__half2*)&Cl[mg * 1024 + ncol] = __halves2half2(l0, l1);
            }
        }
    }
}

// ================= heads finalize =================
__global__ void heads_fin(const float* __restrict__ bs, const float* __restrict__ br) {
    int m = blockIdx.x * 256 + threadIdx.x;
    const float* p = &g_hp[(size_t)m * 24];
    float s = 0.f, r0 = 0.f, r1 = 0.f;
#pragma unroll
    for (int b = 0; b < 8; b++) { s += p[b * 3]; r0 += p[b * 3 + 1]; r1 += p[b * 3 + 2]; }
    float logit = s + bs[0];
    g_logits[m] = logit;
    unsigned bb = __float_as_uint(logit);
    g_keys[m] = (bb & 0x80000000u) ? ~bb : (bb | 0x80000000u);
    g_regv[m] = make_float2(r0 + br[0], r1 + br[1]);
}

// ================= radix select =================
__global__ void rs_hist(int shift) {
    __shared__ unsigned hc[256];
    int t = threadIdx.x;
    hc[t] = 0;
    __syncthreads();
    int m = blockIdx.x * 256 + t;
    unsigned key = g_keys[m];
    if ((key & g_maskbits) == g_prefix)
        atomicAdd(&hc[(key >> shift) & 0xFFu], 1u);
    __syncthreads();
    if (hc[t]) atomicAdd(&g_counts[t], hc[t]);
}

__global__ void rs_scan(int shift) {
    int want = g_want;
    unsigned cum = 0;
    int sel = 0;
    for (int b = 255; b >= 0; b--) {
        unsigned c = g_counts[b];
        if (cum + c >= (unsigned)want) { sel = b; g_want = want - (int)cum; break; }
        cum += c;
    }
    g_prefix |= ((unsigned)sel) << shift;
    g_maskbits |= 0xFFu << shift;
    for (int b = 0; b < 256; b++) g_counts[b] = 0;
}

__global__ void rs_gather() {
    int m = blockIdx.x * 256 + threadIdx.x;
    unsigned key = g_keys[m];
    if (key >= g_prefix) {
        int p = atomicAdd(&g_ncand, 1);
        if (p < CAND_CAP)
            g_cand[p] = ((unsigned long long)key << 32) | (unsigned)(~m);
    }
}

// ================= bitonic sort =================
__global__ void sort_kernel() {
    __shared__ unsigned long long s[CAND_CAP];
    int tid = threadIdx.x;
    for (int i = tid; i < CAND_CAP; i += 1024) s[i] = g_cand[i];
    __syncthreads();
    for (int k = 2; k <= CAND_CAP; k <<= 1) {
        for (int j = k >> 1; j > 0; j >>= 1) {
#pragma unroll
            for (int q = 0; q < 4; q++) {
                int t = tid + q * 1024;
                int ixj = t ^ j;
                if (ixj > t) {
                    unsigned long long a = s[t], b = s[ixj];
                    bool seg = (t & k) == 0;
                    if (seg ? (a < b) : (a > b)) { s[t] = b; s[ixj] = a; }
                }
            }
            __syncthreads();
        }
    }
    for (int i = tid; i < KTOP; i += 1024)
        g_topidx[i] = ~((unsigned)(s[i] & 0xFFFFFFFFull));
}

// ================= NMS (tiled) + parallel top-500 selection =================
__global__ void nms_kernel(float* __restrict__ d_out) {
    __shared__ float sy[KTOP], sx[KTOP], slog[KTOP];
    __shared__ unsigned char supp[KTOP];
    __shared__ float tky[32], tkx[32];
    __shared__ int tkn;
    __shared__ int pk[2048];
    __shared__ int sel[MAXOUT];
    __shared__ float selsc[MAXOUT];
    int tid = threadIdx.x;
    for (int i = tid; i < KTOP; i += 1024) {
        unsigned idx = g_topidx[i];
        int y = idx >> 8;
        int x = idx & 255;
        float2 r = g_regv[idx];
        sy[i] = (float)y + 0.5f + r.x;
        sx[i] = (float)x + 0.5f + r.y;
        slog[i] = g_logits[idx];
        supp[i] = 0;
    }
    __syncthreads();

    const int NT = (KTOP + 31) / 32;   // 63 tiles
    for (int t = 0; t < NT; t++) {
        int base = t * 32;
        int cnt = min(32, KTOP - base);
        if (tid < 32) {
            bool inr = tid < cnt;
            float y = inr ? sy[base + tid] : 1e30f;
            float x = inr ? sx[base + tid] : 1e30f;
            int sup = inr ? (int)supp[base + tid] : 1;
            for (int i = 0; i < cnt; i++) {
                float yi = __shfl_sync(0xFFFFFFFFu, y, i);
                float xi = __shfl_sync(0xFFFFFFFFu, x, i);
                int si = __shfl_sync(0xFFFFFFFFu, sup, i);
                if (!si && tid > i) {
                    float dy = y - yi, dx = x - xi;
                    if (dy * dy + dx * dx < 1.f) sup = 1;
                }
            }
            if (inr) supp[base + tid] = (unsigned char)sup;
            unsigned keptmask = __ballot_sync(0xFFFFFFFFu, inr && !sup);
            if (tid == 0) tkn = __popc(keptmask);
            if (inr && !sup) {
                int p = __popc(keptmask & ((1u << tid) - 1u));
                tky[p] = y; tkx[p] = x;
            }
        }
        __syncthreads();
        int nk = tkn;
        if (nk > 0) {
            for (int j = base + 32 + tid; j < KTOP; j += 1024) {
                if (!supp[j]) {
                    float y = sy[j], x = sx[j];
                    bool s = false;
                    for (int k = 0; k < nk; k++) {
                        float dy = y - tky[k], dx = x - tkx[k];
                        s |= (dy * dy + dx * dx < 1.f);
                    }
                    if (s) supp[j] = 1;
                }
            }
        }
        __syncthreads();
    }

    // inclusive prefix scan of kept flags over 2048 (Hillis-Steele, 2 elems/thread)
    {
        int i0 = tid, i1 = tid + 1024;
        pk[i0] = (i0 < KTOP) ? (supp[i0] ? 0 : 1) : 0;
        pk[i1] = (i1 < KTOP) ? (supp[i1] ? 0 : 1) : 0;
        __syncthreads();
        for (int off = 1; off < 2048; off <<= 1) {
            int v0 = (i0 >= off) ? pk[i0 - off] : 0;
            int v1 = (i1 >= off) ? pk[i1 - off] : 0;
            __syncthreads();
            pk[i0] += v0; pk[i1] += v1;
            __syncthreads();
        }
    }
    int ktot = pk[KTOP - 1];
    int kmin = min(ktot, MAXOUT);
    for (int i = tid; i < KTOP; i += 1024) {
        if (!supp[i]) {
            int rank = pk[i] - 1;
            if (rank < MAXOUT) { sel[rank] = i; selsc[rank] = 1.f / (1.f + expf(-slog[i])); }
        } else {
            int pos = kmin + (i + 1 - pk[i]) - 1;
            if (pos < MAXOUT) { sel[pos] = i; selsc[pos] = -1.f; }
        }
    }
    __syncthreads();

    if (tid < MAXOUT) {
        int i = sel[tid];
        d_out[OFF_SCORES + tid] = selsc[tid];
        d_out[OFF_DEC + 2 * tid] = sy[i] * 4.f;
        d_out[OFF_DEC + 2 * tid + 1] = sx[i] * 4.f;
        float ry = rintf(sy[i] * 2.f - 24.f);
        float rx = rintf(sx[i] * 2.f - 24.f);
        int syi = (int)fminf(fmaxf(ry, 0.f), (float)(HS - CROP));
        int sxi = (int)fminf(fmaxf(rx, 0.f), (float)(WSEG - CROP));
        g_start[2 * tid] = syi;
        g_start[2 * tid + 1] = sxi;
    }
}

// ================= instance conv1 as HMMA implicit GEMM =================
#define CB_STRIDE 592
#define CB_BYTES (64 * CB_STRIDE)
#define CA_BYTES (256 * ASTRIDE)
#define CSMEM_TOTAL (CB_BYTES + 2 * CA_BYTES)

__global__ __launch_bounds__(256, 2) void convi_mma(
    const float* __restrict__ bi)
{
    extern __shared__ char smem[];
    uint32_t sb = smem_to_u32(smem);
    int tid = threadIdx.x;
    int wid = tid >> 5, lane = tid & 31;
    int wm = wid & 3, wn = wid >> 2;
    int crop = blockIdx.x;
    int strip = blockIdx.y;
    int p0 = strip * 256;

    int sy = g_start[2 * crop], sx = g_start[2 * crop + 1];

    for (int i = tid; i < 64 * 288; i += 256) {
        int co = i / 288, k = i % 288;
        *(__half*)(smem + co * CB_STRIDE + k * 2) = g_wiT[i];
    }

    auto stageA = [&](int kt, int buf) {
        uint32_t base = sb + CB_BYTES + buf * CA_BYTES;
        int dy = kt / 3, dx = kt % 3;
#pragma unroll
        for (int q = 0; q < 4; q++) {
            int idx = tid + q * 256;
            int pix = idx >> 2, ch = idx & 3;
            int p = p0 + pix;
            int r = p / 48, c = p - r * 48;
            int rin = r + dy - 1, cin = c + dx - 1;
            bool valid = ((unsigned)rin < 48u) && ((unsigned)cin < 48u);
            size_t off = valid ? (((size_t)(sy + rin) * 512 + (sx + cin)) * 32 + ch * 8) : 0;
            unsigned sz = valid ? 16u : 0u;
            uint32_t sdst = base + pix * ASTRIDE + ch * 16;
            CP_ASYNC16(sdst, g_segh + off, sz);
        }
    };

    float acc[4][2][4], acc2[4][2][4];
#pragma unroll
    for (int mt = 0; mt < 4; mt++)
#pragma unroll
        for (int nt = 0; nt < 2; nt++)
#pragma unroll
            for (int i = 0; i < 4; i++) { acc[mt][nt][i] = 0.f; acc2[mt][nt][i] = 0.f; }

    int r8 = lane & 7;
    int a_rowoff = ((lane >> 3) & 1) * 8 + r8;
    int a_k16 = (lane >> 4) & 1;
    int b_rowoff = ((lane >> 4) & 1) * 8 + r8;
    int b_k16 = (lane >> 3) & 1;

    stageA(0, 0);
    CP_COMMIT();
    __syncthreads();

    for (int kt = 0; kt < 9; kt++) {
        if (kt + 1 < 9) { stageA(kt + 1, (kt + 1) & 1); CP_COMMIT(); CP_WAIT1(); }
        else { CP_WAIT0(); }
        __syncthreads();

        uint32_t abase = sb + CB_BYTES + (kt & 1) * CA_BYTES;
#pragma unroll
        for (int ks = 0; ks < 2; ks++) {
            uint32_t a[4][4], b[4][2];
#pragma unroll
            for (int mt = 0; mt < 4; mt++) {
                uint32_t aaddr = abase + (wm * 64 + mt * 16 + a_rowoff) * ASTRIDE
                               + ks * 32 + a_k16 * 16;
                LDSM_X4(a[mt][0], a[mt][1], a[mt][2], a[mt][3], aaddr);
            }
#pragma unroll
            for (int pr = 0; pr < 2; pr++) {
                uint32_t baddr = sb + (wn * 32 + pr * 16 + b_rowoff) * CB_STRIDE
                               + kt * 64 + ks * 32 + b_k16 * 16;
                uint32_t t0, t1, t2, t3;
                LDSM_X4(t0, t1, t2, t3, baddr);
                b[2 * pr][0] = t0; b[2 * pr][1] = t1;
                b[2 * pr + 1][0] = t2; b[2 * pr + 1][1] = t3;
            }
#pragma unroll
            for (int mt = 0; mt < 4; mt++) {
#pragma unroll
                for (int nt = 0; nt < 2; nt++) {
                    MMA16816(acc[mt][nt], a[mt], b[nt][0], b[nt][1]);
                    MMA16816(acc2[mt][nt], a[mt], b[2 + nt][0], b[2 + nt][1]);
                }
            }
        }
        __syncthreads();
    }

    int g = lane >> 2, tig = lane & 3;
#pragma unroll
    for (int mt = 0; mt < 4; mt++) {
#pragma unroll
        for (int rh = 0; rh < 2; rh++) {
            int pix = p0 + wm * 64 + mt * 16 + g + rh * 8;
#pragma unroll
            for (int nt = 0; nt < 4; nt++) {
                int n = wn * 32 + nt * 8 + 2 * tig;
                float v0 = (nt < 2) ? acc[mt][nt][rh * 2 + 0] : acc2[mt][nt - 2][rh * 2 + 0];
                float v1 = (nt < 2) ? acc[mt][nt][rh * 2 + 1] : acc2[mt][nt - 2][rh * 2 + 1];
                float d0 = fmaxf(v0 + bi[n], 0.f);
                float d1 = fmaxf(v1 + bi[n + 1], 0.f);
                *(__half2*)&g_h[((size_t)crop * 2304 + pix) * 64 + n] =
                    __halves2half2(__float2half(d0), __float2half(d1));
            }
        }
    }
}

// ================= instance conv2 =================
#define SMEM_O_FLOATS (10 * 48 * 65 + 576)
__global__ __launch_bounds__(384) void convo_kernel(
    const float* __restrict__ Wo, const float* __restrict__ bo, float* __restrict__ d_out)
{
    extern __shared__ float sm[];
    float* h_s = sm;
    float* wsm = sm + 10 * 48 * 65;

    int crop = blockIdx.x;
    int strip = blockIdx.y;
    int tid = threadIdx.x;

    for (int i = tid; i < 576; i += 384) wsm[i] = Wo[i];

    int r0 = strip * 8 - 1;
    for (int id = tid; id < 10 * 48 * 64; id += 384) {
        int co = id & 63;
        int rest = id >> 6;
        int cc = rest % 48;
        int rr = rest / 48;
        int rin = r0 + rr;
        float v = 0.f;
        if ((unsigned)rin < 48u)
            v = __half2float(g_h[(((size_t)crop * 48 + rin) * 48 + cc) * 64 + co]);
        h_s[(rr * 48 + cc) * 65 + co] = v;
    }
    __syncthreads();

    int r = tid / 48;
    int c = tid % 48;
    float acc = bo[0];
#pragma unroll
    for (int dy = 0; dy < 3; dy++) {
#pragma unroll
        for (int dx = 0; dx < 3; dx++) {
            int hc = c + dx - 1;
            if ((unsigned)hc < 48u) {
                const float* hb = h_s + ((r + dy) * 48 + hc) * 65;
                const float* wb = wsm + (dy * 3 + dx) * 64;
#pragma unroll 8
                for (int ci = 0; ci < 64; ci++) acc += hb[ci] * wb[ci];
            }
        }
    }
    float o = 1.f / (1.f + expf(-acc));
    int r_out = strip * 8 + r;
    size_t oi = ((size_t)crop * 48 + r_out) * 48 + c;
    d_out[OFF_INST + oi] = o;
    int syi = g_start[2 * crop], sxi = g_start[2 * crop + 1];
    d_out[OFF_COORD + oi * 2] = (float)(syi + r_out);
    d_out[OFF_COORD + oi * 2 + 1] = (float)(sxi + c);
}

// ================= launch =================
extern "C" void kernel_launch(void* const* d_in, const int* in_sizes, int n_in,
                              void* d_out, int out_size)
{
    const float* det = (const float*)d_in[0];
    const float* seg = (const float*)d_in[1];
    const float* Wc  = (const float*)d_in[2];
    const float* bc  = (const float*)d_in[3];
    const float* Wfc = (const float*)d_in[4];
    const float* bfc = (const float*)d_in[5];
    const float* Ws  = (const float*)d_in[6];
    const float* bs  = (const float*)d_in[7];
    const float* Wr  = (const float*)d_in[8];
    const float* br  = (const float*)d_in[9];
    const float* Wi  = (const float*)d_in[10];
    const float* bi  = (const float*)d_in[11];
    const float* Wo  = (const float*)d_in[12];
    const float* bo  = (const float*)d_in[13];
    float* out = (float*)d_out;

    __half *p_wt1h, *p_wt1l, *p_wt2h, *p_wt2l, *p_x1h, *p_x1l, *p_deth, *p_detl;
    cudaGetSymbolAddress((void**)&p_deth, g_deth);
    cudaGetSymbolAddress((void**)&p_detl, g_detl);
    cudaGetSymbolAddress((void**)&p_wt1h, g_wt1h);
    cudaGetSymbolAddress((void**)&p_wt1l, g_wt1l);
    cudaGetSymbolAddress((void**)&p_wt2h, g_wt2h);
    cudaGetSymbolAddress((void**)&p_wt2l, g_wt2l);
    cudaGetSymbolAddress((void**)&p_x1h, g_x1h);
    cudaGetSymbolAddress((void**)&p_x1l, g_x1l);

    cudaFuncSetAttribute(gemm_tc<1,0>, cudaFuncAttributeMaxDynamicSharedMemorySize, GSMEM_TOTAL);
    cudaFuncSetAttribute(gemm_tc<0,1>, cudaFuncAttributeMaxDynamicSharedMemorySize, GSMEM_TOTAL);
    cudaFuncSetAttribute(convi_mma, cudaFuncAttributeMaxDynamicSharedMemorySize, CSMEM_TOTAL);
    cudaFuncSetAttribute(convo_kernel, cudaFuncAttributeMaxDynamicSharedMemorySize,
                         SMEM_O_FLOATS * 4);

    // order chosen so gemm_tc<1,0> is launch index 3 (the ncu capture slot)
    split_det_kernel<<<(NPIX * CD) / 512, 512>>>(det);
    split_wT_kernel<<<dim3(36, 32), dim3(32, 8)>>>(Wc, p_wt1h, p_wt1l, 1152);
    split_wT_kernel<<<dim3(32, 32), dim3(32, 8)>>>(Wfc, p_wt2h, p_wt2l, 1024);

    gemm_tc<1,0><<<dim3(8, 512), 256, GSMEM_TOTAL>>>(
        p_deth, p_detl, p_wt1h, p_wt1l, bc, nullptr, nullptr, p_x1h, p_x1l, 1152);

    init_kernel<<<1, 256>>>();
    split_seg_kernel<<<(HS * WSEG * CS) / 512, 512>>>(seg);
    prep_wiT_kernel<<<64, 128>>>(Wi);

    gemm_tc<0,1><<<dim3(8, 512), 256, GSMEM_TOTAL>>>(
        p_x1h, p_x1l, p_wt2h, p_wt2l, bfc, Ws, Wr, nullptr, nullptr, 1024);
    heads_fin<<<256, 256>>>(bs, br);

    int shifts[4] = {24, 16, 8, 0};
    for (int p = 0; p < 4; p++) {
        rs_hist<<<256, 256>>>(shifts[p]);
        rs_scan<<<1, 1>>>(shifts[p]);
    }
    rs_gather<<<256, 256>>>();
    sort_kernel<<<1, 1024>>>();

    nms_kernel<<<1, 1024>>>(out);

    convi_mma<<<dim3(500, 9), 256, CSMEM_TOTAL>>>(bi);
    convo_kernel<<<dim3(500, 6), 384, SMEM_O_FLOATS * 4>>>(Wo, bo, out);
}